// round 11
// baseline (speedup 1.0000x reference)
#include <cuda_runtime.h>
#include <cuda_fp16.h>
#include <cstdint>

#define B_  8
#define C_  512
#define H_  8
#define DH  64
#define N_  1024
#define BH_ 64

// ---------------- scratch (__device__ globals; no allocs) ----------------
__device__ __half g_Wh[3 * C_ * C_], g_Wl[3 * C_ * C_];          // [sel][o][c]
__device__ __half g_XTh[B_ * N_ * C_], g_XTl[B_ * N_ * C_];      // [b][n][c]
__device__ __half g_rhh[H_ * 32 * DH], g_rhl[H_ * 32 * DH];      // [h][i][d] (rh^T)
__device__ __half g_rwh[H_ * 32 * DH], g_rwl[H_ * 32 * DH];      // [h][j][d] (rw^T)
__device__ __half g_qh[BH_ * N_ * DH], g_ql[BH_ * N_ * DH];      // [bh][n][d]
__device__ __half g_k[BH_ * N_ * DH];                            // [bh][n][d] single fp16
__device__ __half g_v[(size_t)B_ * C_ * N_];                     // [b][c][n]
__device__ float  g_U[(size_t)BH_ * 32 * N_];                    // [bh][i][m]
__device__ float  g_W[(size_t)BH_ * 32 * N_];                    // [bh][j][m]

// ---------------- helpers ----------------
__device__ __forceinline__ uint32_t s2u(const void* p) {
    uint32_t a;
    asm("{ .reg .u64 t; cvta.to.shared.u64 t, %1; cvt.u32.u64 %0, t; }" : "=r"(a) : "l"(p));
    return a;
}
__device__ __forceinline__ void cpasync16(uint32_t dst, const void* src) {
    asm volatile("cp.async.ca.shared.global [%0], [%1], 16;" :: "r"(dst), "l"(src));
}
__device__ __forceinline__ void cp_commit() {
    asm volatile("cp.async.commit_group;" ::: "memory");
}
__device__ __forceinline__ void cp_wait0() {
    asm volatile("cp.async.wait_group 0;" ::: "memory");
}
__device__ __forceinline__ void ldsm4(uint32_t* r, uint32_t addr) {
    asm volatile("ldmatrix.sync.aligned.m8n8.x4.shared.b16 {%0,%1,%2,%3}, [%4];"
                 : "=r"(r[0]), "=r"(r[1]), "=r"(r[2]), "=r"(r[3]) : "r"(addr));
}
__device__ __forceinline__ void mma_f16(float* c, const uint32_t* a, const uint32_t* b) {
    asm volatile(
        "mma.sync.aligned.m16n8k16.row.col.f32.f16.f16.f32 "
        "{%0,%1,%2,%3},{%4,%5,%6,%7},{%8,%9},{%0,%1,%2,%3};"
        : "+f"(c[0]), "+f"(c[1]), "+f"(c[2]), "+f"(c[3])
        : "r"(a[0]), "r"(a[1]), "r"(a[2]), "r"(a[3]), "r"(b[0]), "r"(b[1]));
}
// 128B-row tiles ([rows][64] half), XOR swizzle on 16B granules
__device__ __forceinline__ uint32_t swz(uint32_t base, int row, int g) {
    return base + row * 128 + ((g ^ (row & 7)) << 4);
}
// 256B-row tiles ([rows][128] half)
__device__ __forceinline__ uint32_t swzv(uint32_t base, int row, int g) {
    return base + row * 256 + ((g ^ (row & 7)) << 4);
}
__device__ __forceinline__ void split_h(float a, __half& h, __half& l) {
    h = __float2half_rn(a);
    l = __float2half_rn(a - __half2float(h));
}
__device__ __forceinline__ uint32_t pack2(float a, float b) {
    __half2 h = __floats2half2_rn(a, b);
    return *(uint32_t*)&h;
}

// ---------------- prep kernels ----------------
__global__ __launch_bounds__(256) void prep_w(const float* __restrict__ wq,
                                              const float* __restrict__ wk,
                                              const float* __restrict__ wv) {
    int idx = blockIdx.x * 256 + threadIdx.x;
    int sel = idx >> 18, rc = idx & 262143;
    const float* W = sel == 0 ? wq : (sel == 1 ? wk : wv);
    __half h, l;
    split_h(W[rc], h, l);
    g_Wh[idx] = h; g_Wl[idx] = l;
}

__global__ void prep_xt(const float* __restrict__ x) {
    __shared__ float sm[32][33];
    int b = blockIdx.z, c0 = blockIdx.y * 32, n0 = blockIdx.x * 32;
    int tx = threadIdx.x, ty = threadIdx.y;
    sm[ty][tx] = x[((size_t)b * C_ + c0 + ty) * N_ + n0 + tx];
    __syncthreads();
    __half h, l;
    split_h(sm[tx][ty], h, l);
    size_t off = ((size_t)b * N_ + n0 + ty) * C_ + c0 + tx;
    g_XTh[off] = h; g_XTl[off] = l;
}

__global__ __launch_bounds__(256) void prep_r(const float* __restrict__ rh,
                                              const float* __restrict__ rw) {
    int idx = blockIdx.x * 256 + threadIdx.x;   // [h][i][d], 16384 total
    int h = idx >> 11, i = (idx >> 6) & 31, d = idx & 63;
    __half hh, ll;
    split_h(rh[(h * DH + d) * 32 + i], hh, ll);
    g_rhh[idx] = hh; g_rhl[idx] = ll;
    split_h(rw[(h * DH + d) * 32 + i], hh, ll);
    g_rwh[idx] = hh; g_rwl[idx] = ll;
}

// ---------------- stage 1: QKV projection (mma.sync, hi/lo) --------------
// out[o,n] = sum_c W[o,c] x[c,n] + bias[o]; computed as (XT @ W^T)
// CTA tile 64n x 256o (finer grains for scheduler balance), 512 thr =
// 16 warps (4 wm x 4 wn), warp tile 16x64. Q: 3 terms; V: 2; K: 1.
// Stage (80KB): XH +0, XL +8K, WH +16K, WL +48K ; 2 stages.
#define QKV_STG 81920
#define SMEM_QKV 163840
__global__ __launch_bounds__(512) void qkv_mma(const float* __restrict__ bq,
                                               const float* __restrict__ bk,
                                               const float* __restrict__ bv) {
    extern __shared__ char smem[];
    uint32_t sb = s2u(smem);
    int t = threadIdx.x, lane = t & 31, wid = t >> 5;
    int wm = wid & 3, wn = wid >> 2;
    int n0 = blockIdx.x * 64, o0 = blockIdx.y * 256;
    int z = blockIdx.z, b = z / 3, sel = z - b * 3;

    const __half* XH = g_XTh + (size_t)b * N_ * C_ + (size_t)n0 * C_;
    const __half* XL = g_XTl + (size_t)b * N_ * C_ + (size_t)n0 * C_;
    const __half* WH = g_Wh + (size_t)sel * C_ * C_ + (size_t)o0 * C_;
    const __half* WL = g_Wl + (size_t)sel * C_ * C_ + (size_t)o0 * C_;

    float acc[8][4];
#pragma unroll
    for (int j = 0; j < 8; j++)
#pragma unroll
        for (int k = 0; k < 4; k++) acc[j][k] = 0.f;

    auto issue = [&](int cc, int buf) {
        uint32_t st = sb + buf * QKV_STG;
        // X tiles: 2 x 512 cp (64 rows x 8 granules each)
#pragma unroll
        for (int i = 0; i < 2; i++) {
            int idx = t + i * 512;
            int which = idx >> 9, r = (idx & 511) >> 3, g = idx & 7;
            const __half* src = (which ? XL : XH) + cc * 64 + (size_t)r * C_ + g * 8;
            cpasync16(swz(st + which * 8192, r, g), src);
        }
        // W tiles: 2 x 2048 cp
#pragma unroll
        for (int i = 0; i < 8; i++) {
            int idx = t + i * 512;
            int which = idx >> 11, r = (idx & 2047) >> 3, g = idx & 7;
            const __half* src = (which ? WL : WH) + cc * 64 + (size_t)r * C_ + g * 8;
            cpasync16(swz(st + 16384 + which * 32768, r, g), src);
        }
        cp_commit();
    };

    issue(0, 0);
    for (int cc = 0; cc < 8; cc++) {
        cp_wait0();
        __syncthreads();
        if (cc < 7) issue(cc + 1, (cc + 1) & 1);
        uint32_t st = sb + (cc & 1) * QKV_STG;
#pragma unroll
        for (int ks = 0; ks < 4; ks++) {
            int acol = 2 * ks + (lane >> 4);
            int arow = wm * 16 + (lane & 15);
            uint32_t aH[4], aL[4];
            ldsm4(aH, swz(st, arow, acol));
            ldsm4(aL, swz(st + 8192, arow, acol));
            uint32_t bf[4][4];
#pragma unroll
            for (int nb = 0; nb < 4; nb++)
                ldsm4(bf[nb], swz(st + 16384, wn * 64 + nb * 16 + (lane & 15), acol));
            // pass 1: xH * wH  (all)
#pragma unroll
            for (int nb = 0; nb < 4; nb++) {
                uint32_t lo[2] = {bf[nb][0], bf[nb][2]}, hi[2] = {bf[nb][1], bf[nb][3]};
                mma_f16(acc[nb * 2], aH, lo); mma_f16(acc[nb * 2 + 1], aH, hi);
            }
            // pass 2: xL * wH  (Q, V)
            if (sel != 1) {
#pragma unroll
                for (int nb = 0; nb < 4; nb++) {
                    uint32_t lo[2] = {bf[nb][0], bf[nb][2]}, hi[2] = {bf[nb][1], bf[nb][3]};
                    mma_f16(acc[nb * 2], aL, lo); mma_f16(acc[nb * 2 + 1], aL, hi);
                }
            }
            // pass 3: xH * wL  (Q only)
            if (sel == 0) {
#pragma unroll
                for (int nb = 0; nb < 4; nb++)
                    ldsm4(bf[nb], swz(st + 49152, wn * 64 + nb * 16 + (lane & 15), acol));
#pragma unroll
                for (int nb = 0; nb < 4; nb++) {
                    uint32_t lo[2] = {bf[nb][0], bf[nb][2]}, hi[2] = {bf[nb][1], bf[nb][3]};
                    mma_f16(acc[nb * 2], aH, lo); mma_f16(acc[nb * 2 + 1], aH, hi);
                }
            }
        }
    }

    const float* bias = sel == 0 ? bq : (sel == 1 ? bk : bv);
#pragma unroll
    for (int nf = 0; nf < 8; nf++) {
        int og = o0 + wn * 64 + nf * 8 + (lane & 3) * 2;
        float b0 = bias[og], b1 = bias[og + 1];
        int r0 = n0 + wm * 16 + (lane >> 2);
        float v0 = acc[nf][0] + b0, v1 = acc[nf][1] + b1;
        float v2 = acc[nf][2] + b0, v3 = acc[nf][3] + b1;
        if (sel == 2) {
            __half* vp = g_v + ((size_t)b * C_ + og) * N_;
            vp[r0] = __float2half_rn(v0);
            vp[r0 + 8] = __float2half_rn(v2);
            vp[N_ + r0] = __float2half_rn(v1);
            vp[N_ + r0 + 8] = __float2half_rn(v3);
        } else if (sel == 1) {
            int hh = og >> 6, d = og & 63;
            __half* kp = g_k + (size_t)(b * H_ + hh) * N_ * DH;
            *(__half2*)&kp[(size_t)r0 * DH + d] =
                __halves2half2(__float2half_rn(v0), __float2half_rn(v1));
            *(__half2*)&kp[(size_t)(r0 + 8) * DH + d] =
                __halves2half2(__float2half_rn(v2), __float2half_rn(v3));
        } else {
            int hh = og >> 6, d = og & 63;
            __half* TH = g_qh + (size_t)(b * H_ + hh) * N_ * DH;
            __half* TL = g_ql + (size_t)(b * H_ + hh) * N_ * DH;
            __half h0, l0, h1, l1;
            split_h(v0, h0, l0); split_h(v1, h1, l1);
            *(__half2*)&TH[(size_t)r0 * DH + d] = __halves2half2(h0, h1);
            *(__half2*)&TL[(size_t)r0 * DH + d] = __halves2half2(l0, l1);
            split_h(v2, h0, l0); split_h(v3, h1, l1);
            *(__half2*)&TH[(size_t)(r0 + 8) * DH + d] = __halves2half2(h0, h1);
            *(__half2*)&TL[(size_t)(r0 + 8) * DH + d] = __halves2half2(l0, l1);
        }
    }
}

// ---------------- stage 1.5: U = rh^T q, W = rw^T q (per bh) --------------
#define SMEM_UW 65536
__global__ __launch_bounds__(256) void uw_mma() {
    extern __shared__ char smem[];
    uint32_t sb = s2u(smem);
    int t = threadIdx.x, lane = t & 31, wid = t >> 5;
    int wm = wid & 1, wn = wid >> 1;
    int m0 = blockIdx.x * 128;
    int bh = blockIdx.y, h = bh & 7;

#pragma unroll
    for (int pp = 0; pp < 2; pp++) {
        int idx = t + pp * 256;
        int row = idx >> 3, g = idx & 7;
        int off = h * 2048 + (row & 31) * 64 + g * 8;
        const __half* srcH = (row < 32 ? g_rhh : g_rwh) + off;
        const __half* srcL = (row < 32 ? g_rhl : g_rwl) + off;
        cpasync16(swz(sb, row, g), srcH);
        cpasync16(swz(sb + 8192, row, g), srcL);
    }
    const __half* QHp = g_qh + ((size_t)bh * N_ + m0) * DH;
    const __half* QLp = g_ql + ((size_t)bh * N_ + m0) * DH;
#pragma unroll
    for (int pp = 0; pp < 4; pp++) {
        int idx = t + pp * 256;
        int row = idx >> 3, g = idx & 7;
        cpasync16(swz(sb + 16384, row, g), QHp + (size_t)row * DH + g * 8);
        cpasync16(swz(sb + 32768, row, g), QLp + (size_t)row * DH + g * 8);
    }
    cp_commit();
    cp_wait0();
    __syncthreads();

    float acc[2][4][4];
#pragma unroll
    for (int i = 0; i < 2; i++)
#pragma unroll
        for (int j = 0; j < 4; j++)
#pragma unroll
            for (int k = 0; k < 4; k++) acc[i][j][k] = 0.f;

#pragma unroll
    for (int ks = 0; ks < 4; ks++) {
        int acol = 2 * ks + (lane >> 4);
        uint32_t aH[2][4], aL[2][4];
#pragma unroll
        for (int mi = 0; mi < 2; mi++) {
            int arow = wm * 32 + mi * 16 + (lane & 15);
            ldsm4(aH[mi], swz(sb, arow, acol));
            ldsm4(aL[mi], swz(sb + 8192, arow, acol));
        }
        uint32_t bH[2][4], bL[2][4];
#pragma unroll
        for (int nbb = 0; nbb < 2; nbb++) {
            int brow = wn * 32 + nbb * 16 + (lane & 15);
            ldsm4(bH[nbb], swz(sb + 16384, brow, acol));
            ldsm4(bL[nbb], swz(sb + 32768, brow, acol));
        }
#pragma unroll
        for (int nbb = 0; nbb < 2; nbb++) {
            uint32_t lo[2] = {bH[nbb][0], bH[nbb][2]}, hi[2] = {bH[nbb][1], bH[nbb][3]};
            mma_f16(acc[0][nbb * 2], aH[0], lo); mma_f16(acc[0][nbb * 2 + 1], aH[0], hi);
            mma_f16(acc[1][nbb * 2], aH[1], lo); mma_f16(acc[1][nbb * 2 + 1], aH[1], hi);
        }
#pragma unroll
        for (int nbb = 0; nbb < 2; nbb++) {
            uint32_t lo[2] = {bH[nbb][0], bH[nbb][2]}, hi[2] = {bH[nbb][1], bH[nbb][3]};
            mma_f16(acc[0][nbb * 2], aL[0], lo); mma_f16(acc[0][nbb * 2 + 1], aL[0], hi);
            mma_f16(acc[1][nbb * 2], aL[1], lo); mma_f16(acc[1][nbb * 2 + 1], aL[1], hi);
        }
#pragma unroll
        for (int nbb = 0; nbb < 2; nbb++) {
            uint32_t lo[2] = {bL[nbb][0], bL[nbb][2]}, hi[2] = {bL[nbb][1], bL[nbb][3]};
            mma_f16(acc[0][nbb * 2], aH[0], lo); mma_f16(acc[0][nbb * 2 + 1], aH[0], hi);
            mma_f16(acc[1][nbb * 2], aH[1], lo); mma_f16(acc[1][nbb * 2 + 1], aH[1], hi);
        }
    }

    float* base = wm == 0 ? g_U : g_W;
#pragma unroll
    for (int mi = 0; mi < 2; mi++)
#pragma unroll
        for (int nf = 0; nf < 4; nf++) {
            int rr = (mi * 16 + (lane >> 2)) & 31;
            int col = m0 + wn * 32 + nf * 8 + (lane & 3) * 2;
            float2 v0 = {acc[mi][nf][0], acc[mi][nf][1]};
            float2 v1 = {acc[mi][nf][2], acc[mi][nf][3]};
            *(float2*)&base[((size_t)bh * 32 + rr) * N_ + col] = v0;
            *(float2*)&base[((size_t)bh * 32 + rr + 8) * N_ + col] = v1;
        }
}

// ---------------- stage 2-4 fused flash attention ------------------------
// 256 thr = 8 warps, 64-query tiles (1024 CTAs), forced 1 CTA/SM (smem pad)
// so 1024/148 = 6.92 waves -> ~1% tail. Warp (wq4, hv): 16 q rows, 64-key
// half. K/V double-buffered 2x32KB; U/W double-buffered 2x19008.
// smem: QH 0..8K | KV 8192 + p*32768 (K+0, V+16K) | UW 73728 + p*19008 | pad.
#define FA_KV 8192
#define FA_UW 73728
#define UW_STRIDE 19008
#define SMEM_FU 114688
__global__ __launch_bounds__(256) void attn_fused(float* __restrict__ out) {
    extern __shared__ char smem[];
    uint32_t sb = s2u(smem);
    int t = threadIdx.x, lane = t & 31, w = t >> 5;
    int wq4 = w & 3;          // query-row group (16 rows each)
    int hv = w >> 2;          // key half: 0 or 1
    int q0 = blockIdx.x * 64;
    int bh = blockIdx.y, b = bh >> 3, h = bh & 7;

    const __half* QH = g_qh + (size_t)bh * N_ * DH;
    const __half* K  = g_k + (size_t)bh * N_ * DH;
    const __half* V  = g_v + (size_t)(b * C_ + h * DH) * N_;   // [64][1024]
    const float*  Ug = g_U + (size_t)bh * 32 * N_;
    const float*  Wg = g_W + ((size_t)bh * 32 + (q0 >> 5)) * N_;

    // QH rows q0..q0+63
    {
#pragma unroll
        for (int p = 0; p < 2; p++) {
            int idx = t + p * 256;
            int row = idx >> 3, g = idx & 7;
            cpasync16(swz(sb, row, g), QH + (size_t)(q0 + row) * DH + g * 8);
        }
        cp_commit();
    }

    auto prefetch = [&](int j, int p) {
        int n0 = j * 128;
        uint32_t bb = sb + FA_KV + p * 32768;
#pragma unroll
        for (int pp = 0; pp < 4; pp++) {
            int idx = t + pp * 256;
            int row = idx >> 3, g = idx & 7;
            cpasync16(swz(bb, row, g), K + (size_t)(n0 + row) * DH + g * 8);
        }
#pragma unroll
        for (int pp = 0; pp < 4; pp++) {
            int idx = t + pp * 256;
            int row = idx >> 4, g = idx & 15;   // V [64][128] tile
            cpasync16(swzv(bb + 16384, row, g), V + (size_t)row * N_ + n0 + g * 8);
        }
        uint32_t uw = sb + FA_UW + p * UW_STRIDE;
#pragma unroll
        for (int pp = 0; pp < 4; pp++) {
            int idx = t + pp * 256;
            int row = idx >> 5, g = idx & 31;   // U: 32 rows (528B rows)
            cpasync16(uw + row * 528 + g * 16, Ug + (size_t)row * N_ + n0 + g * 4);
        }
        if (t < 64) {
            int row = t >> 5, g = t & 31;       // W: 2 rows
            cpasync16(uw + 16896 + row * 528 + g * 16, Wg + (size_t)row * N_ + n0 + g * 4);
        }
        cp_commit();
    };

    prefetch(0, 0);

    int rbase = wq4 * 16 + (lane >> 2);          // 0..63
    int i0 = rbase & 31, i1 = (rbase + 8) & 31;
    int jl0 = rbase >> 5, jl1 = (rbase + 8) >> 5;

    float m0 = -1e30f, m1 = -1e30f, l0 = 0.f, l1 = 0.f;
    float y[8][4];
#pragma unroll
    for (int i = 0; i < 8; i++)
#pragma unroll
        for (int j = 0; j < 4; j++) y[i][j] = 0.f;

    for (int j = 0; j < 8; j++) {
        cp_wait0();
        __syncthreads();
        int p = j & 1;
        if (j < 7) prefetch(j + 1, p ^ 1);
        uint32_t bb = sb + FA_KV + p * 32768;
        const char* uwc = smem + FA_UW + p * UW_STRIDE;

        // ---- scores: single term qh·k, 16 q rows x 64-key half ----
        float s[8][4];
#pragma unroll
        for (int f = 0; f < 8; f++)
#pragma unroll
            for (int k = 0; k < 4; k++) s[f][k] = 0.f;

#pragma unroll
        for (int ks = 0; ks < 4; ks++) {
            int arow = wq4 * 16 + (lane & 15), acol = 2 * ks + (lane >> 4);
            uint32_t aQH[4];
            ldsm4(aQH, swz(sb, arow, acol));
            uint32_t bf[4][4];
#pragma unroll
            for (int nb = 0; nb < 4; nb++)
                ldsm4(bf[nb], swz(bb, hv * 64 + nb * 16 + (lane & 15), acol));
#pragma unroll
            for (int nb = 0; nb < 4; nb++) {
                uint32_t lo[2] = {bf[nb][0], bf[nb][2]}, hi[2] = {bf[nb][1], bf[nb][3]};
                mma_f16(s[nb * 2], aQH, lo); mma_f16(s[nb * 2 + 1], aQH, hi);
            }
        }

        // ---- add positional term from staged U/W ----
#pragma unroll
        for (int nb = 0; nb < 4; nb++)
#pragma unroll
            for (int half = 0; half < 2; half++) {
                int col = hv * 64 + nb * 16 + half * 8 + (lane & 3) * 2;
                float2 u0 = *(const float2*)(uwc + i0 * 528 + col * 4);
                float2 u1 = *(const float2*)(uwc + i1 * 528 + col * 4);
                float2 w0 = *(const float2*)(uwc + 16896 + jl0 * 528 + col * 4);
                float2 w1 = *(const float2*)(uwc + 16896 + jl1 * 528 + col * 4);
                int f = nb * 2 + half;
                s[f][0] += u0.x + w0.x;
                s[f][1] += u0.y + w0.y;
                s[f][2] += u1.x + w1.x;
                s[f][3] += u1.y + w1.y;
            }

        // ---- per-warp online softmax (its key half only) ----
        float tmax0 = -1e30f, tmax1 = -1e30f;
#pragma unroll
        for (int f = 0; f < 8; f++) {
            tmax0 = fmaxf(tmax0, fmaxf(s[f][0], s[f][1]));
            tmax1 = fmaxf(tmax1, fmaxf(s[f][2], s[f][3]));
        }
        tmax0 = fmaxf(tmax0, __shfl_xor_sync(0xffffffffu, tmax0, 1));
        tmax0 = fmaxf(tmax0, __shfl_xor_sync(0xffffffffu, tmax0, 2));
        tmax1 = fmaxf(tmax1, __shfl_xor_sync(0xffffffffu, tmax1, 1));
        tmax1 = fmaxf(tmax1, __shfl_xor_sync(0xffffffffu, tmax1, 2));
        float mn0 = fmaxf(m0, tmax0), mn1 = fmaxf(m1, tmax1);
        float sc0 = __expf(m0 - mn0), sc1 = __expf(m1 - mn1);
        m0 = mn0; m1 = mn1;

        float ts0 = 0.f, ts1 = 0.f;
        uint32_t pf[8][2];
#pragma unroll
        for (int f = 0; f < 8; f++) {
            float p0 = __expf(s[f][0] - mn0), p1 = __expf(s[f][1] - mn0);
            float p2 = __expf(s[f][2] - mn1), p3 = __expf(s[f][3] - mn1);
            ts0 += p0 + p1; ts1 += p2 + p3;
            pf[f][0] = pack2(p0, p1);
            pf[f][1] = pack2(p2, p3);
        }
        ts0 += __shfl_xor_sync(0xffffffffu, ts0, 1);
        ts0 += __shfl_xor_sync(0xffffffffu, ts0, 2);
        ts1 += __shfl_xor_sync(0xffffffffu, ts1, 1);
        ts1 += __shfl_xor_sync(0xffffffffu, ts1, 2);
        l0 = l0 * sc0 + ts0;
        l1 = l1 * sc1 + ts1;
#pragma unroll
        for (int nf = 0; nf < 8; nf++) {
            y[nf][0] *= sc0; y[nf][1] *= sc0;
            y[nf][2] *= sc1; y[nf][3] *= sc1;
        }

        // ---- y += P @ V^T over this warp's 64 keys ----
#pragma unroll
        for (int ks = 0; ks < 4; ks++) {
            uint32_t a[4] = {pf[2 * ks][0], pf[2 * ks][1], pf[2 * ks + 1][0], pf[2 * ks + 1][1]};
            int vcol = hv * 8 + 2 * ks + (lane >> 4);
#pragma unroll
            for (int nb = 0; nb < 4; nb++) {
                uint32_t bf[4];
                ldsm4(bf, swzv(bb + 16384, nb * 16 + (lane & 15), vcol));
                uint32_t blo[2] = {bf[0], bf[2]}, bhi[2] = {bf[1], bf[3]};
                mma_f16(y[nb * 2], a, blo);
                mma_f16(y[nb * 2 + 1], a, bhi);
            }
        }
    }

    // ---- epilogue: pairwise flash merge via smem, then store ----
    __syncthreads();   // KV/UW regions now free
    float* yst = (float*)(smem + FA_KV);            // [64 d][68 q] = 17408 B
    float* yb = (float*)(smem + FA_KV + 17408);     // [64 q][68 d] = 17408 B
    float* mb = (float*)(smem + FA_KV + 34816);     // 64 f32
    float* lb = mb + 64;
    int rl = rbase;

    if (hv == 1) {
#pragma unroll
        for (int nf = 0; nf < 8; nf++) {
            int d0 = nf * 8 + (lane & 3) * 2;
            yb[rl * 68 + d0] = y[nf][0];
            yb[rl * 68 + d0 + 1] = y[nf][1];
            yb[(rl + 8) * 68 + d0] = y[nf][2];
            yb[(rl + 8) * 68 + d0 + 1] = y[nf][3];
        }
        if ((lane & 3) == 0) {
            mb[rl] = m0; lb[rl] = l0;
            mb[rl + 8] = m1; lb[rl + 8] = l1;
        }
    }
    __syncthreads();

    if (hv == 0) {
        float mB0 = mb[rl], lB0 = lb[rl], mB1 = mb[rl + 8], lB1 = lb[rl + 8];
        float mf0 = fmaxf(m0, mB0), mf1 = fmaxf(m1, mB1);
        float fa0 = __expf(m0 - mf0), fb0 = __expf(mB0 - mf0);
        float fa1 = __expf(m1 - mf1), fb1 = __expf(mB1 - mf1);
        float inv0 = 1.f / (l0 * fa0 + lB0 * fb0);
        float inv1 = 1.f / (l1 * fa1 + lB1 * fb1);
        float sa0 = fa0 * inv0, sb0 = fb0 * inv0;
        float sa1 = fa1 * inv1, sb1 = fb1 * inv1;
#pragma unroll
        for (int nf = 0; nf < 8; nf++) {
            int d0 = nf * 8 + (lane & 3) * 2;
            yst[d0 * 68 + rl]       = y[nf][0] * sa0 + yb[rl * 68 + d0] * sb0;
            yst[(d0 + 1) * 68 + rl] = y[nf][1] * sa0 + yb[rl * 68 + d0 + 1] * sb0;
            yst[d0 * 68 + rl + 8]       = y[nf][2] * sa1 + yb[(rl + 8) * 68 + d0] * sb1;
            yst[(d0 + 1) * 68 + rl + 8] = y[nf][3] * sa1 + yb[(rl + 8) * 68 + d0 + 1] * sb1;
        }
    }
    __syncthreads();
    float* O = out + (size_t)(b * C_ + h * DH) * N_ + q0;
    for (int i = t; i < 1024; i += 256) {
        int d = i >> 4, qg = i & 15;
        float4 vv = *(float4*)&yst[d * 68 + qg * 4];
        *(float4*)&O[(size_t)d * N_ + qg * 4] = vv;
    }
}

// ---------------- launch ----------------
extern "C" void kernel_launch(void* const* d_in, const int* in_sizes, int n_in,
                              void* d_out, int out_size) {
    const float* x  = (const float*)d_in[0];
    const float* wq = (const float*)d_in[1];
    const float* bq = (const float*)d_in[2];
    const float* wk = (const float*)d_in[3];
    const float* bk = (const float*)d_in[4];
    const float* wv = (const float*)d_in[5];
    const float* bv = (const float*)d_in[6];
    const float* rh = (const float*)d_in[7];
    const float* rw = (const float*)d_in[8];

    cudaFuncSetAttribute(qkv_mma, cudaFuncAttributeMaxDynamicSharedMemorySize, SMEM_QKV);
    cudaFuncSetAttribute(uw_mma, cudaFuncAttributeMaxDynamicSharedMemorySize, SMEM_UW);
    cudaFuncSetAttribute(attn_fused, cudaFuncAttributeMaxDynamicSharedMemorySize, SMEM_FU);

    prep_w<<<(3 * C_ * C_) / 256, 256>>>(wq, wk, wv);
    prep_xt<<<dim3(N_ / 32, C_ / 32, B_), dim3(32, 32)>>>(x);
    prep_r<<<H_ * 32 * DH / 256, 256>>>(rh, rw);

    qkv_mma<<<dim3(16, 2, 24), 512, SMEM_QKV>>>(bq, bk, bv);
    uw_mma<<<dim3(8, BH_), 256, SMEM_UW>>>();
    attn_fused<<<dim3(16, BH_), 256, SMEM_FU>>>((float*)d_out);
}

// round 12
// speedup vs baseline: 1.0929x; 1.0929x over previous
#include <cuda_runtime.h>
#include <cuda_fp16.h>
#include <cstdint>

#define B_  8
#define C_  512
#define H_  8
#define DH  64
#define N_  1024
#define BH_ 64

// ---------------- scratch (__device__ globals; no allocs) ----------------
__device__ __half g_Wh[3 * C_ * C_], g_Wl[3 * C_ * C_];          // [sel][o][c]
__device__ __half g_XTh[B_ * N_ * C_], g_XTl[B_ * N_ * C_];      // [b][n][c]
__device__ __half g_rhh[H_ * 32 * DH], g_rhl[H_ * 32 * DH];      // [h][i][d] (rh^T)
__device__ __half g_rwh[H_ * 32 * DH], g_rwl[H_ * 32 * DH];      // [h][j][d] (rw^T)
__device__ __half g_qh[BH_ * N_ * DH], g_ql[BH_ * N_ * DH];      // [bh][n][d]
__device__ __half g_k[BH_ * N_ * DH];                            // [bh][n][d] single fp16
__device__ __half g_v[(size_t)B_ * C_ * N_];                     // [b][c][n]
__device__ float  g_U[(size_t)BH_ * 32 * N_];                    // [bh][i][m]
__device__ float  g_W[(size_t)BH_ * 32 * N_];                    // [bh][j][m]

// ---------------- helpers ----------------
__device__ __forceinline__ uint32_t s2u(const void* p) {
    uint32_t a;
    asm("{ .reg .u64 t; cvta.to.shared.u64 t, %1; cvt.u32.u64 %0, t; }" : "=r"(a) : "l"(p));
    return a;
}
__device__ __forceinline__ void cpasync16(uint32_t dst, const void* src) {
    asm volatile("cp.async.ca.shared.global [%0], [%1], 16;" :: "r"(dst), "l"(src));
}
__device__ __forceinline__ void cp_commit() {
    asm volatile("cp.async.commit_group;" ::: "memory");
}
__device__ __forceinline__ void cp_wait0() {
    asm volatile("cp.async.wait_group 0;" ::: "memory");
}
__device__ __forceinline__ void ldsm4(uint32_t* r, uint32_t addr) {
    asm volatile("ldmatrix.sync.aligned.m8n8.x4.shared.b16 {%0,%1,%2,%3}, [%4];"
                 : "=r"(r[0]), "=r"(r[1]), "=r"(r[2]), "=r"(r[3]) : "r"(addr));
}
__device__ __forceinline__ void mma_f16(float* c, const uint32_t* a, const uint32_t* b) {
    asm volatile(
        "mma.sync.aligned.m16n8k16.row.col.f32.f16.f16.f32 "
        "{%0,%1,%2,%3},{%4,%5,%6,%7},{%8,%9},{%0,%1,%2,%3};"
        : "+f"(c[0]), "+f"(c[1]), "+f"(c[2]), "+f"(c[3])
        : "r"(a[0]), "r"(a[1]), "r"(a[2]), "r"(a[3]), "r"(b[0]), "r"(b[1]));
}
// 128B-row tiles ([rows][64] half), XOR swizzle on 16B granules
__device__ __forceinline__ uint32_t swz(uint32_t base, int row, int g) {
    return base + row * 128 + ((g ^ (row & 7)) << 4);
}
// 256B-row tiles ([rows][128] half)
__device__ __forceinline__ uint32_t swzv(uint32_t base, int row, int g) {
    return base + row * 256 + ((g ^ (row & 7)) << 4);
}
__device__ __forceinline__ void split_h(float a, __half& h, __half& l) {
    h = __float2half_rn(a);
    l = __float2half_rn(a - __half2float(h));
}
__device__ __forceinline__ uint32_t cvt2h(float hi, float lo) {
    uint32_t r;
    asm("cvt.rn.f16x2.f32 %0, %1, %2;" : "=r"(r) : "f"(hi), "f"(lo));
    return r;
}
__device__ __forceinline__ uint32_t ex2h2(uint32_t x) {
    uint32_t r;
    asm("ex2.approx.f16x2 %0, %1;" : "=r"(r) : "r"(x));
    return r;
}

// ---------------- prep kernels ----------------
__global__ __launch_bounds__(256) void prep_w(const float* __restrict__ wq,
                                              const float* __restrict__ wk,
                                              const float* __restrict__ wv) {
    int idx = blockIdx.x * 256 + threadIdx.x;
    int sel = idx >> 18, rc = idx & 262143;
    const float* W = sel == 0 ? wq : (sel == 1 ? wk : wv);
    __half h, l;
    split_h(W[rc], h, l);
    g_Wh[idx] = h; g_Wl[idx] = l;
}

__global__ void prep_xt(const float* __restrict__ x) {
    __shared__ float sm[32][33];
    int b = blockIdx.z, c0 = blockIdx.y * 32, n0 = blockIdx.x * 32;
    int tx = threadIdx.x, ty = threadIdx.y;
    sm[ty][tx] = x[((size_t)b * C_ + c0 + ty) * N_ + n0 + tx];
    __syncthreads();
    __half h, l;
    split_h(sm[tx][ty], h, l);
    size_t off = ((size_t)b * N_ + n0 + ty) * C_ + c0 + tx;
    g_XTh[off] = h; g_XTl[off] = l;
}

__global__ __launch_bounds__(256) void prep_r(const float* __restrict__ rh,
                                              const float* __restrict__ rw) {
    int idx = blockIdx.x * 256 + threadIdx.x;   // [h][i][d], 16384 total
    int h = idx >> 11, i = (idx >> 6) & 31, d = idx & 63;
    __half hh, ll;
    split_h(rh[(h * DH + d) * 32 + i], hh, ll);
    g_rhh[idx] = hh; g_rhl[idx] = ll;
    split_h(rw[(h * DH + d) * 32 + i], hh, ll);
    g_rwh[idx] = hh; g_rwl[idx] = ll;
}

// ---------------- stage 1: QKV projection (mma.sync, hi/lo) --------------
// CTA tile 128n x 256o, 512 thr = 16 warps (4 wm x 4 wn), warp tile 32x64.
// Q: 3 terms; V: 2 terms; K: 1 term.
#define QKV_STG 98304
#define SMEM_QKV 196608
__global__ __launch_bounds__(512) void qkv_mma(const float* __restrict__ bq,
                                               const float* __restrict__ bk,
                                               const float* __restrict__ bv) {
    extern __shared__ char smem[];
    uint32_t sb = s2u(smem);
    int t = threadIdx.x, lane = t & 31, wid = t >> 5;
    int wm = wid & 3, wn = wid >> 2;
    int n0 = blockIdx.x * 128, o0 = blockIdx.y * 256;
    int z = blockIdx.z, b = z / 3, sel = z - b * 3;

    const __half* XH = g_XTh + (size_t)b * N_ * C_ + (size_t)n0 * C_;
    const __half* XL = g_XTl + (size_t)b * N_ * C_ + (size_t)n0 * C_;
    const __half* WH = g_Wh + (size_t)sel * C_ * C_ + (size_t)o0 * C_;
    const __half* WL = g_Wl + (size_t)sel * C_ * C_ + (size_t)o0 * C_;

    float acc[2][8][4];
#pragma unroll
    for (int i = 0; i < 2; i++)
#pragma unroll
        for (int j = 0; j < 8; j++)
#pragma unroll
            for (int k = 0; k < 4; k++) acc[i][j][k] = 0.f;

    auto issue = [&](int cc, int buf) {
        uint32_t st = sb + buf * QKV_STG;
#pragma unroll
        for (int i = 0; i < 4; i++) {
            int idx = t + i * 512;
            int which = idx >> 10, r = (idx & 1023) >> 3, g = idx & 7;
            const __half* src = (which ? XL : XH) + cc * 64 + (size_t)r * C_ + g * 8;
            cpasync16(swz(st + which * 16384, r, g), src);
        }
#pragma unroll
        for (int i = 0; i < 8; i++) {
            int idx = t + i * 512;
            int which = idx >> 11, r = (idx & 2047) >> 3, g = idx & 7;
            const __half* src = (which ? WL : WH) + cc * 64 + (size_t)r * C_ + g * 8;
            cpasync16(swz(st + 32768 + which * 32768, r, g), src);
        }
        cp_commit();
    };

    issue(0, 0);
    for (int cc = 0; cc < 8; cc++) {
        cp_wait0();
        __syncthreads();
        if (cc < 7) issue(cc + 1, (cc + 1) & 1);
        uint32_t st = sb + (cc & 1) * QKV_STG;
#pragma unroll
        for (int ks = 0; ks < 4; ks++) {
            int acol = 2 * ks + (lane >> 4);
            uint32_t aH[2][4], aL[2][4];
#pragma unroll
            for (int mi = 0; mi < 2; mi++) {
                int arow = wm * 32 + mi * 16 + (lane & 15);
                ldsm4(aH[mi], swz(st, arow, acol));
                ldsm4(aL[mi], swz(st + 16384, arow, acol));
            }
            uint32_t bf[4][4];
#pragma unroll
            for (int nb = 0; nb < 4; nb++)
                ldsm4(bf[nb], swz(st + 32768, wn * 64 + nb * 16 + (lane & 15), acol));
            // pass 1: xH * wH  (all)
#pragma unroll
            for (int nb = 0; nb < 4; nb++) {
                uint32_t lo[2] = {bf[nb][0], bf[nb][2]}, hi[2] = {bf[nb][1], bf[nb][3]};
                mma_f16(acc[0][nb * 2], aH[0], lo); mma_f16(acc[0][nb * 2 + 1], aH[0], hi);
                mma_f16(acc[1][nb * 2], aH[1], lo); mma_f16(acc[1][nb * 2 + 1], aH[1], hi);
            }
            // pass 2: xL * wH  (Q, V)
            if (sel != 1) {
#pragma unroll
                for (int nb = 0; nb < 4; nb++) {
                    uint32_t lo[2] = {bf[nb][0], bf[nb][2]}, hi[2] = {bf[nb][1], bf[nb][3]};
                    mma_f16(acc[0][nb * 2], aL[0], lo); mma_f16(acc[0][nb * 2 + 1], aL[0], hi);
                    mma_f16(acc[1][nb * 2], aL[1], lo); mma_f16(acc[1][nb * 2 + 1], aL[1], hi);
                }
            }
            // pass 3: xH * wL  (Q only)
            if (sel == 0) {
#pragma unroll
                for (int nb = 0; nb < 4; nb++)
                    ldsm4(bf[nb], swz(st + 65536, wn * 64 + nb * 16 + (lane & 15), acol));
#pragma unroll
                for (int nb = 0; nb < 4; nb++) {
                    uint32_t lo[2] = {bf[nb][0], bf[nb][2]}, hi[2] = {bf[nb][1], bf[nb][3]};
                    mma_f16(acc[0][nb * 2], aH[0], lo); mma_f16(acc[0][nb * 2 + 1], aH[0], hi);
                    mma_f16(acc[1][nb * 2], aH[1], lo); mma_f16(acc[1][nb * 2 + 1], aH[1], hi);
                }
            }
        }
    }

    const float* bias = sel == 0 ? bq : (sel == 1 ? bk : bv);
#pragma unroll
    for (int mi = 0; mi < 2; mi++)
#pragma unroll
        for (int nf = 0; nf < 8; nf++) {
            int og = o0 + wn * 64 + nf * 8 + (lane & 3) * 2;
            float b0 = bias[og], b1 = bias[og + 1];
            int r0 = n0 + wm * 32 + mi * 16 + (lane >> 2);
            float v0 = acc[mi][nf][0] + b0, v1 = acc[mi][nf][1] + b1;
            float v2 = acc[mi][nf][2] + b0, v3 = acc[mi][nf][3] + b1;
            if (sel == 2) {
                __half* vp = g_v + ((size_t)b * C_ + og) * N_;
                vp[r0] = __float2half_rn(v0);
                vp[r0 + 8] = __float2half_rn(v2);
                vp[N_ + r0] = __float2half_rn(v1);
                vp[N_ + r0 + 8] = __float2half_rn(v3);
            } else if (sel == 1) {
                int hh = og >> 6, d = og & 63;
                __half* kp = g_k + (size_t)(b * H_ + hh) * N_ * DH;
                *(__half2*)&kp[(size_t)r0 * DH + d] =
                    __halves2half2(__float2half_rn(v0), __float2half_rn(v1));
                *(__half2*)&kp[(size_t)(r0 + 8) * DH + d] =
                    __halves2half2(__float2half_rn(v2), __float2half_rn(v3));
            } else {
                int hh = og >> 6, d = og & 63;
                __half* TH = g_qh + (size_t)(b * H_ + hh) * N_ * DH;
                __half* TL = g_ql + (size_t)(b * H_ + hh) * N_ * DH;
                __half h0, l0, h1, l1;
                split_h(v0, h0, l0); split_h(v1, h1, l1);
                *(__half2*)&TH[(size_t)r0 * DH + d] = __halves2half2(h0, h1);
                *(__half2*)&TL[(size_t)r0 * DH + d] = __halves2half2(l0, l1);
                split_h(v2, h0, l0); split_h(v3, h1, l1);
                *(__half2*)&TH[(size_t)(r0 + 8) * DH + d] = __halves2half2(h0, h1);
                *(__half2*)&TL[(size_t)(r0 + 8) * DH + d] = __halves2half2(l0, l1);
            }
        }
}

// ---------------- stage 1.5: U = rh^T q, W = rw^T q (per bh) --------------
#define SMEM_UW 65536
__global__ __launch_bounds__(256) void uw_mma() {
    extern __shared__ char smem[];
    uint32_t sb = s2u(smem);
    int t = threadIdx.x, lane = t & 31, wid = t >> 5;
    int wm = wid & 1, wn = wid >> 1;
    int m0 = blockIdx.x * 128;
    int bh = blockIdx.y, h = bh & 7;

#pragma unroll
    for (int pp = 0; pp < 2; pp++) {
        int idx = t + pp * 256;
        int row = idx >> 3, g = idx & 7;
        int off = h * 2048 + (row & 31) * 64 + g * 8;
        const __half* srcH = (row < 32 ? g_rhh : g_rwh) + off;
        const __half* srcL = (row < 32 ? g_rhl : g_rwl) + off;
        cpasync16(swz(sb, row, g), srcH);
        cpasync16(swz(sb + 8192, row, g), srcL);
    }
    const __half* QHp = g_qh + ((size_t)bh * N_ + m0) * DH;
    const __half* QLp = g_ql + ((size_t)bh * N_ + m0) * DH;
#pragma unroll
    for (int pp = 0; pp < 4; pp++) {
        int idx = t + pp * 256;
        int row = idx >> 3, g = idx & 7;
        cpasync16(swz(sb + 16384, row, g), QHp + (size_t)row * DH + g * 8);
        cpasync16(swz(sb + 32768, row, g), QLp + (size_t)row * DH + g * 8);
    }
    cp_commit();
    cp_wait0();
    __syncthreads();

    float acc[2][4][4];
#pragma unroll
    for (int i = 0; i < 2; i++)
#pragma unroll
        for (int j = 0; j < 4; j++)
#pragma unroll
            for (int k = 0; k < 4; k++) acc[i][j][k] = 0.f;

#pragma unroll
    for (int ks = 0; ks < 4; ks++) {
        int acol = 2 * ks + (lane >> 4);
        uint32_t aH[2][4], aL[2][4];
#pragma unroll
        for (int mi = 0; mi < 2; mi++) {
            int arow = wm * 32 + mi * 16 + (lane & 15);
            ldsm4(aH[mi], swz(sb, arow, acol));
            ldsm4(aL[mi], swz(sb + 8192, arow, acol));
        }
        uint32_t bH[2][4], bL[2][4];
#pragma unroll
        for (int nbb = 0; nbb < 2; nbb++) {
            int brow = wn * 32 + nbb * 16 + (lane & 15);
            ldsm4(bH[nbb], swz(sb + 16384, brow, acol));
            ldsm4(bL[nbb], swz(sb + 32768, brow, acol));
        }
#pragma unroll
        for (int nbb = 0; nbb < 2; nbb++) {
            uint32_t lo[2] = {bH[nbb][0], bH[nbb][2]}, hi[2] = {bH[nbb][1], bH[nbb][3]};
            mma_f16(acc[0][nbb * 2], aH[0], lo); mma_f16(acc[0][nbb * 2 + 1], aH[0], hi);
            mma_f16(acc[1][nbb * 2], aH[1], lo); mma_f16(acc[1][nbb * 2 + 1], aH[1], hi);
        }
#pragma unroll
        for (int nbb = 0; nbb < 2; nbb++) {
            uint32_t lo[2] = {bH[nbb][0], bH[nbb][2]}, hi[2] = {bH[nbb][1], bH[nbb][3]};
            mma_f16(acc[0][nbb * 2], aL[0], lo); mma_f16(acc[0][nbb * 2 + 1], aL[0], hi);
            mma_f16(acc[1][nbb * 2], aL[1], lo); mma_f16(acc[1][nbb * 2 + 1], aL[1], hi);
        }
#pragma unroll
        for (int nbb = 0; nbb < 2; nbb++) {
            uint32_t lo[2] = {bL[nbb][0], bL[nbb][2]}, hi[2] = {bL[nbb][1], bL[nbb][3]};
            mma_f16(acc[0][nbb * 2], aH[0], lo); mma_f16(acc[0][nbb * 2 + 1], aH[0], hi);
            mma_f16(acc[1][nbb * 2], aH[1], lo); mma_f16(acc[1][nbb * 2 + 1], aH[1], hi);
        }
    }

    float* base = wm == 0 ? g_U : g_W;
#pragma unroll
    for (int mi = 0; mi < 2; mi++)
#pragma unroll
        for (int nf = 0; nf < 4; nf++) {
            int rr = (mi * 16 + (lane >> 2)) & 31;
            int col = m0 + wn * 32 + nf * 8 + (lane & 3) * 2;
            float2 v0 = {acc[mi][nf][0], acc[mi][nf][1]};
            float2 v1 = {acc[mi][nf][2], acc[mi][nf][3]};
            *(float2*)&base[((size_t)bh * 32 + rr) * N_ + col] = v0;
            *(float2*)&base[((size_t)bh * 32 + rr + 8) * N_ + col] = v1;
        }
}

// ---------------- stage 2-4 fused flash attention ------------------------
// 256 thr = 8 warps, 64-query tiles, 2 CTAs/SM (R9 config). Warp pair
// (w, w+4): same 16 query rows, opposite 64-key halves. exp via
// ex2.approx.f16x2 (half the MUFU ops); row-sum l via ones-MMA.
// smem: QH 0..8K | KV bufs 8K + p*32K (K +0, V +16K) | U 73728 | W 90624.
#define FA_KV 8192
#define FA_U 73728
#define FA_W 90624
#define SMEM_FU 91712
__global__ __launch_bounds__(256, 2) void attn_fused(float* __restrict__ out) {
    extern __shared__ char smem[];
    uint32_t sb = s2u(smem);
    int t = threadIdx.x, lane = t & 31, w = t >> 5;
    int wq4 = w & 3;          // query-row group (16 rows each)
    int hv = w >> 2;          // key half: 0 or 1
    int q0 = blockIdx.x * 64;
    int bh = blockIdx.y, b = bh >> 3, h = bh & 7;

    const __half* QH = g_qh + (size_t)bh * N_ * DH;
    const __half* K  = g_k + (size_t)bh * N_ * DH;
    const __half* V  = g_v + (size_t)(b * C_ + h * DH) * N_;   // [64][1024]
    const float*  Ug = g_U + (size_t)bh * 32 * N_;
    const float*  Wg = g_W + ((size_t)bh * 32 + (q0 >> 5)) * N_;

    // QH rows q0..q0+63
    {
#pragma unroll
        for (int p = 0; p < 2; p++) {
            int idx = t + p * 256;
            int row = idx >> 3, g = idx & 7;
            cpasync16(swz(sb, row, g), QH + (size_t)(q0 + row) * DH + g * 8);
        }
        cp_commit();
    }

    auto prefetch_kv = [&](int j, int p) {
        int n0 = j * 128;
        uint32_t bb = sb + FA_KV + p * 32768;
#pragma unroll
        for (int pp = 0; pp < 4; pp++) {
            int idx = t + pp * 256;
            int row = idx >> 3, g = idx & 7;
            cpasync16(swz(bb, row, g), K + (size_t)(n0 + row) * DH + g * 8);
        }
#pragma unroll
        for (int pp = 0; pp < 4; pp++) {
            int idx = t + pp * 256;
            int row = idx >> 4, g = idx & 15;   // V [64][128] tile
            cpasync16(swzv(bb + 16384, row, g), V + (size_t)row * N_ + n0 + g * 8);
        }
        cp_commit();
    };
    auto prefetch_uw = [&](int j) {
        int n0 = j * 128;
#pragma unroll
        for (int pp = 0; pp < 4; pp++) {
            int idx = t + pp * 256;
            int row = idx >> 5, g = idx & 31;   // U: 32 rows (528B rows)
            cpasync16(sb + FA_U + row * 528 + g * 16, Ug + (size_t)row * N_ + n0 + g * 4);
        }
        if (t < 64) {
            int row = t >> 5, g = t & 31;       // W: 2 rows
            cpasync16(sb + FA_W + row * 528 + g * 16, Wg + (size_t)row * N_ + n0 + g * 4);
        }
        cp_commit();
    };

    prefetch_kv(0, 0);
    prefetch_uw(0);

    int rbase = wq4 * 16 + (lane >> 2);          // 0..63
    int i0 = rbase & 31, i1 = (rbase + 8) & 31;
    int jl0 = rbase >> 5, jl1 = (rbase + 8) >> 5;

    const float L2E = 1.4426950408889634f;
    const uint32_t ONES2 = 0x3C003C00u;          // fp16 {1, 1}
    uint32_t onesb[2] = {ONES2, ONES2};

    float m0 = -1e30f, m1 = -1e30f;
    float lacc[4] = {0.f, 0.f, 0.f, 0.f};
    float y[8][4];
#pragma unroll
    for (int i = 0; i < 8; i++)
#pragma unroll
        for (int j = 0; j < 4; j++) y[i][j] = 0.f;

    for (int j = 0; j < 8; j++) {
        cp_wait0();
        __syncthreads();
        int p = j & 1;
        if (j < 7) prefetch_kv(j + 1, p ^ 1);
        uint32_t bb = sb + FA_KV + p * 32768;

        // ---- scores: single term qh·k, 16 q rows x 64-key half ----
        float s[8][4];
#pragma unroll
        for (int f = 0; f < 8; f++)
#pragma unroll
            for (int k = 0; k < 4; k++) s[f][k] = 0.f;

#pragma unroll
        for (int ks = 0; ks < 4; ks++) {
            int arow = wq4 * 16 + (lane & 15), acol = 2 * ks + (lane >> 4);
            uint32_t aQH[4];
            ldsm4(aQH, swz(sb, arow, acol));
            uint32_t bf[4][4];
#pragma unroll
            for (int nb = 0; nb < 4; nb++)
                ldsm4(bf[nb], swz(bb, hv * 64 + nb * 16 + (lane & 15), acol));
#pragma unroll
            for (int nb = 0; nb < 4; nb++) {
                uint32_t lo[2] = {bf[nb][0], bf[nb][2]}, hi[2] = {bf[nb][1], bf[nb][3]};
                mma_f16(s[nb * 2], aQH, lo); mma_f16(s[nb * 2 + 1], aQH, hi);
            }
        }

        // ---- add positional term from staged U/W (single buffer) ----
#pragma unroll
        for (int nb = 0; nb < 4; nb++)
#pragma unroll
            for (int half = 0; half < 2; half++) {
                int col = hv * 64 + nb * 16 + half * 8 + (lane & 3) * 2;
                float2 u0 = *(const float2*)(smem + FA_U + i0 * 528 + col * 4);
                float2 u1 = *(const float2*)(smem + FA_U + i1 * 528 + col * 4);
                float2 w0 = *(const float2*)(smem + FA_W + jl0 * 528 + col * 4);
                float2 w1 = *(const float2*)(smem + FA_W + jl1 * 528 + col * 4);
                int f = nb * 2 + half;
                s[f][0] += u0.x + w0.x;
                s[f][1] += u0.y + w0.y;
                s[f][2] += u1.x + w1.x;
                s[f][3] += u1.y + w1.y;
            }
        __syncthreads();                  // all warps done with U/W(j)
        if (j < 7) prefetch_uw(j + 1);    // overwrite U/W with next tile

        // ---- per-warp online softmax (its key half only) ----
        float tmax0 = -1e30f, tmax1 = -1e30f;
#pragma unroll
        for (int f = 0; f < 8; f++) {
            tmax0 = fmaxf(tmax0, fmaxf(s[f][0], s[f][1]));
            tmax1 = fmaxf(tmax1, fmaxf(s[f][2], s[f][3]));
        }
        tmax0 = fmaxf(tmax0, __shfl_xor_sync(0xffffffffu, tmax0, 1));
        tmax0 = fmaxf(tmax0, __shfl_xor_sync(0xffffffffu, tmax0, 2));
        tmax1 = fmaxf(tmax1, __shfl_xor_sync(0xffffffffu, tmax1, 1));
        tmax1 = fmaxf(tmax1, __shfl_xor_sync(0xffffffffu, tmax1, 2));
        float mn0 = fmaxf(m0, tmax0), mn1 = fmaxf(m1, tmax1);
        float sc0 = __expf(m0 - mn0), sc1 = __expf(m1 - mn1);
        m0 = mn0; m1 = mn1;

        // p = 2^((s - mn) * log2e) via fp16x2 MUFU (2 weights per op)
        float b0s = mn0 * L2E, b1s = mn1 * L2E;
        uint32_t pf[8][2];
#pragma unroll
        for (int f = 0; f < 8; f++) {
            float e0 = fmaf(s[f][0], L2E, -b0s);
            float e1 = fmaf(s[f][1], L2E, -b0s);
            float e2 = fmaf(s[f][2], L2E, -b1s);
            float e3 = fmaf(s[f][3], L2E, -b1s);
            pf[f][0] = ex2h2(cvt2h(e1, e0));
            pf[f][1] = ex2h2(cvt2h(e3, e2));
        }
        lacc[0] *= sc0; lacc[1] *= sc0;
        lacc[2] *= sc1; lacc[3] *= sc1;
#pragma unroll
        for (int nf = 0; nf < 8; nf++) {
            y[nf][0] *= sc0; y[nf][1] *= sc0;
            y[nf][2] *= sc1; y[nf][3] *= sc1;
        }

        // ---- y += P @ V^T; l += P @ ones  (this warp's 64 keys) ----
#pragma unroll
        for (int ks = 0; ks < 4; ks++) {
            uint32_t a[4] = {pf[2 * ks][0], pf[2 * ks][1], pf[2 * ks + 1][0], pf[2 * ks + 1][1]};
            int vcol = hv * 8 + 2 * ks + (lane >> 4);
            mma_f16(lacc, a, onesb);
#pragma unroll
            for (int nb = 0; nb < 4; nb++) {
                uint32_t bf[4];
                ldsm4(bf, swzv(bb + 16384, nb * 16 + (lane & 15), vcol));
                uint32_t blo[2] = {bf[0], bf[2]}, bhi[2] = {bf[1], bf[3]};
                mma_f16(y[nb * 2], a, blo);
                mma_f16(y[nb * 2 + 1], a, bhi);
            }
        }
    }

    float l0 = lacc[0], l1 = lacc[2];

    // ---- epilogue: pairwise flash merge via smem, then store ----
    __syncthreads();   // KV/U region now free
    float* yst = (float*)(smem + FA_KV);            // [64 d][68 q] = 17408 B
    float* yb = (float*)(smem + FA_KV + 17408);     // [64 q][68 d] = 17408 B
    float* mb = (float*)(smem + FA_KV + 34816);     // 64 f32
    float* lb = mb + 64;
    int rl = rbase;

    if (hv == 1) {
#pragma unroll
        for (int nf = 0; nf < 8; nf++) {
            int d0 = nf * 8 + (lane & 3) * 2;
            yb[rl * 68 + d0] = y[nf][0];
            yb[rl * 68 + d0 + 1] = y[nf][1];
            yb[(rl + 8) * 68 + d0] = y[nf][2];
            yb[(rl + 8) * 68 + d0 + 1] = y[nf][3];
        }
        if ((lane & 3) == 0) {
            mb[rl] = m0; lb[rl] = l0;
            mb[rl + 8] = m1; lb[rl + 8] = l1;
        }
    }
    __syncthreads();

    if (hv == 0) {
        float mB0 = mb[rl], lB0 = lb[rl], mB1 = mb[rl + 8], lB1 = lb[rl + 8];
        float mf0 = fmaxf(m0, mB0), mf1 = fmaxf(m1, mB1);
        float fa0 = __expf(m0 - mf0), fb0 = __expf(mB0 - mf0);
        float fa1 = __expf(m1 - mf1), fb1 = __expf(mB1 - mf1);
        float inv0 = 1.f / (l0 * fa0 + lB0 * fb0);
        float inv1 = 1.f / (l1 * fa1 + lB1 * fb1);
        float sa0 = fa0 * inv0, sb0 = fb0 * inv0;
        float sa1 = fa1 * inv1, sb1 = fb1 * inv1;
#pragma unroll
        for (int nf = 0; nf < 8; nf++) {
            int d0 = nf * 8 + (lane & 3) * 2;
            yst[d0 * 68 + rl]       = y[nf][0] * sa0 + yb[rl * 68 + d0] * sb0;
            yst[(d0 + 1) * 68 + rl] = y[nf][1] * sa0 + yb[rl * 68 + d0 + 1] * sb0;
            yst[d0 * 68 + rl + 8]       = y[nf][2] * sa1 + yb[(rl + 8) * 68 + d0] * sb1;
            yst[(d0 + 1) * 68 + rl + 8] = y[nf][3] * sa1 + yb[(rl + 8) * 68 + d0 + 1] * sb1;
        }
    }
    __syncthreads();
    float* O = out + (size_t)(b * C_ + h * DH) * N_ + q0;
    for (int i = t; i < 1024; i += 256) {
        int d = i >> 4, qg = i & 15;
        float4 vv = *(float4*)&yst[d * 68 + qg * 4];
        *(float4*)&O[(size_t)d * N_ + qg * 4] = vv;
    }
}

// ---------------- launch ----------------
extern "C" void kernel_launch(void* const* d_in, const int* in_sizes, int n_in,
                              void* d_out, int out_size) {
    const float* x  = (const float*)d_in[0];
    const float* wq = (const float*)d_in[1];
    const float* bq = (const float*)d_in[2];
    const float* wk = (const float*)d_in[3];
    const float* bk = (const float*)d_in[4];
    const float* wv = (const float*)d_in[5];
    const float* bv = (const float*)d_in[6];
    const float* rh = (const float*)d_in[7];
    const float* rw = (const float*)d_in[8];

    cudaFuncSetAttribute(qkv_mma, cudaFuncAttributeMaxDynamicSharedMemorySize, SMEM_QKV);
    cudaFuncSetAttribute(uw_mma, cudaFuncAttributeMaxDynamicSharedMemorySize, SMEM_UW);
    cudaFuncSetAttribute(attn_fused, cudaFuncAttributeMaxDynamicSharedMemorySize, SMEM_FU);

    prep_w<<<(3 * C_ * C_) / 256, 256>>>(wq, wk, wv);
    prep_xt<<<dim3(N_ / 32, C_ / 32, B_), dim3(32, 32)>>>(x);
    prep_r<<<H_ * 32 * DH / 256, 256>>>(rh, rw);

    qkv_mma<<<dim3(8, 2, 24), 512, SMEM_QKV>>>(bq, bk, bv);
    uw_mma<<<dim3(8, BH_), 256, SMEM_UW>>>();
    attn_fused<<<dim3(16, BH_), 256, SMEM_FU>>>((float*)d_out);
}

// round 13
// speedup vs baseline: 1.1521x; 1.0542x over previous
#include <cuda_runtime.h>
#include <cuda_fp16.h>
#include <cstdint>

#define B_  8
#define C_  512
#define H_  8
#define DH  64
#define N_  1024
#define BH_ 64

// ---------------- scratch (__device__ globals; no allocs) ----------------
__device__ __half g_Wh[3 * C_ * C_], g_Wl[3 * C_ * C_];          // [sel][o][c]
__device__ __half g_XTh[B_ * N_ * C_], g_XTl[B_ * N_ * C_];      // [b][n][c]
__device__ __half g_rhh[H_ * 32 * DH], g_rhl[H_ * 32 * DH];      // [h][i][d] (rh^T)
__device__ __half g_rwh[H_ * 32 * DH], g_rwl[H_ * 32 * DH];      // [h][j][d] (rw^T)
__device__ __half g_qh[BH_ * N_ * DH], g_ql[BH_ * N_ * DH];      // [bh][n][d]
__device__ __half g_k[BH_ * N_ * DH];                            // [bh][n][d] single fp16
__device__ __half g_v[(size_t)B_ * C_ * N_];                     // [b][c][n]
__device__ float  g_U[(size_t)BH_ * 32 * N_];                    // [bh][i][m]
__device__ float  g_W[(size_t)BH_ * 32 * N_];                    // [bh][j][m]

// ---------------- helpers ----------------
__device__ __forceinline__ uint32_t s2u(const void* p) {
    uint32_t a;
    asm("{ .reg .u64 t; cvta.to.shared.u64 t, %1; cvt.u32.u64 %0, t; }" : "=r"(a) : "l"(p));
    return a;
}
__device__ __forceinline__ void cpasync16(uint32_t dst, const void* src) {
    asm volatile("cp.async.ca.shared.global [%0], [%1], 16;" :: "r"(dst), "l"(src));
}
__device__ __forceinline__ void cp_commit() {
    asm volatile("cp.async.commit_group;" ::: "memory");
}
__device__ __forceinline__ void cp_wait0() {
    asm volatile("cp.async.wait_group 0;" ::: "memory");
}
__device__ __forceinline__ void ldsm4(uint32_t* r, uint32_t addr) {
    asm volatile("ldmatrix.sync.aligned.m8n8.x4.shared.b16 {%0,%1,%2,%3}, [%4];"
                 : "=r"(r[0]), "=r"(r[1]), "=r"(r[2]), "=r"(r[3]) : "r"(addr));
}
__device__ __forceinline__ void mma_f16(float* c, const uint32_t* a, const uint32_t* b) {
    asm volatile(
        "mma.sync.aligned.m16n8k16.row.col.f32.f16.f16.f32 "
        "{%0,%1,%2,%3},{%4,%5,%6,%7},{%8,%9},{%0,%1,%2,%3};"
        : "+f"(c[0]), "+f"(c[1]), "+f"(c[2]), "+f"(c[3])
        : "r"(a[0]), "r"(a[1]), "r"(a[2]), "r"(a[3]), "r"(b[0]), "r"(b[1]));
}
// 128B-row tiles ([rows][64] half), XOR swizzle on 16B granules
__device__ __forceinline__ uint32_t swz(uint32_t base, int row, int g) {
    return base + row * 128 + ((g ^ (row & 7)) << 4);
}
// 256B-row tiles ([rows][128] half)
__device__ __forceinline__ uint32_t swzv(uint32_t base, int row, int g) {
    return base + row * 256 + ((g ^ (row & 7)) << 4);
}
__device__ __forceinline__ void split_h(float a, __half& h, __half& l) {
    h = __float2half_rn(a);
    l = __float2half_rn(a - __half2float(h));
}
__device__ __forceinline__ uint32_t cvt2h(float hi, float lo) {
    uint32_t r;
    asm("cvt.rn.f16x2.f32 %0, %1, %2;" : "=r"(r) : "f"(hi), "f"(lo));
    return r;
}
__device__ __forceinline__ uint32_t ex2h2(uint32_t x) {
    uint32_t r;
    asm("ex2.approx.f16x2 %0, %1;" : "=r"(r) : "r"(x));
    return r;
}

// ---------------- prep kernels ----------------
__global__ __launch_bounds__(256) void prep_w(const float* __restrict__ wq,
                                              const float* __restrict__ wk,
                                              const float* __restrict__ wv) {
    int idx = blockIdx.x * 256 + threadIdx.x;
    int sel = idx >> 18, rc = idx & 262143;
    const float* W = sel == 0 ? wq : (sel == 1 ? wk : wv);
    __half h, l;
    split_h(W[rc], h, l);
    g_Wh[idx] = h; g_Wl[idx] = l;
}

__global__ void prep_xt(const float* __restrict__ x) {
    __shared__ float sm[32][33];
    int b = blockIdx.z, c0 = blockIdx.y * 32, n0 = blockIdx.x * 32;
    int tx = threadIdx.x, ty = threadIdx.y;
    sm[ty][tx] = x[((size_t)b * C_ + c0 + ty) * N_ + n0 + tx];
    __syncthreads();
    __half h, l;
    split_h(sm[tx][ty], h, l);
    size_t off = ((size_t)b * N_ + n0 + ty) * C_ + c0 + tx;
    g_XTh[off] = h; g_XTl[off] = l;
}

__global__ __launch_bounds__(256) void prep_r(const float* __restrict__ rh,
                                              const float* __restrict__ rw) {
    int idx = blockIdx.x * 256 + threadIdx.x;   // [h][i][d], 16384 total
    int h = idx >> 11, i = (idx >> 6) & 31, d = idx & 63;
    __half hh, ll;
    split_h(rh[(h * DH + d) * 32 + i], hh, ll);
    g_rhh[idx] = hh; g_rhl[idx] = ll;
    split_h(rw[(h * DH + d) * 32 + i], hh, ll);
    g_rwh[idx] = hh; g_rwl[idx] = ll;
}

// ---------------- stage 1: QKV projection (mma.sync, hi/lo) --------------
// CTA tile 128n x 256o, 512 thr = 16 warps (4 wm x 4 wn), warp tile 32x64.
// Q: 3 terms; V: 2 terms; K: 1 term. LPT dispatch order: Q jobs first,
// then V, then K (z = order*8 + b). Dead tile loads skipped per sel.
#define QKV_STG 98304
#define SMEM_QKV 196608
__global__ __launch_bounds__(512) void qkv_mma(const float* __restrict__ bq,
                                               const float* __restrict__ bk,
                                               const float* __restrict__ bv) {
    extern __shared__ char smem[];
    uint32_t sb = s2u(smem);
    int t = threadIdx.x, lane = t & 31, wid = t >> 5;
    int wm = wid & 3, wn = wid >> 2;
    int n0 = blockIdx.x * 128, o0 = blockIdx.y * 256;
    int z = blockIdx.z;
    int order = z >> 3, b = z & 7;
    int sel = order == 0 ? 0 : (order == 1 ? 2 : 1);   // Q, V, K (LPT)

    const __half* XH = g_XTh + (size_t)b * N_ * C_ + (size_t)n0 * C_;
    const __half* XL = g_XTl + (size_t)b * N_ * C_ + (size_t)n0 * C_;
    const __half* WH = g_Wh + (size_t)sel * C_ * C_ + (size_t)o0 * C_;
    const __half* WL = g_Wl + (size_t)sel * C_ * C_ + (size_t)o0 * C_;

    float acc[2][8][4];
#pragma unroll
    for (int i = 0; i < 2; i++)
#pragma unroll
        for (int j = 0; j < 8; j++)
#pragma unroll
            for (int k = 0; k < 4; k++) acc[i][j][k] = 0.f;

    auto issue = [&](int cc, int buf) {
        uint32_t st = sb + buf * QKV_STG;
#pragma unroll
        for (int i = 0; i < 4; i++) {
            int idx = t + i * 512;
            int which = idx >> 10, r = (idx & 1023) >> 3, g = idx & 7;
            if (which == 1 && sel == 1) continue;          // K: no XL
            const __half* src = (which ? XL : XH) + cc * 64 + (size_t)r * C_ + g * 8;
            cpasync16(swz(st + which * 16384, r, g), src);
        }
#pragma unroll
        for (int i = 0; i < 8; i++) {
            int idx = t + i * 512;
            int which = idx >> 11, r = (idx & 2047) >> 3, g = idx & 7;
            if (which == 1 && sel != 0) continue;          // K,V: no WL
            const __half* src = (which ? WL : WH) + cc * 64 + (size_t)r * C_ + g * 8;
            cpasync16(swz(st + 32768 + which * 32768, r, g), src);
        }
        cp_commit();
    };

    issue(0, 0);
    for (int cc = 0; cc < 8; cc++) {
        cp_wait0();
        __syncthreads();
        if (cc < 7) issue(cc + 1, (cc + 1) & 1);
        uint32_t st = sb + (cc & 1) * QKV_STG;
#pragma unroll
        for (int ks = 0; ks < 4; ks++) {
            int acol = 2 * ks + (lane >> 4);
            uint32_t aH[2][4], aL[2][4];
#pragma unroll
            for (int mi = 0; mi < 2; mi++) {
                int arow = wm * 32 + mi * 16 + (lane & 15);
                ldsm4(aH[mi], swz(st, arow, acol));
                if (sel != 1)
                    ldsm4(aL[mi], swz(st + 16384, arow, acol));
            }
            uint32_t bf[4][4];
#pragma unroll
            for (int nb = 0; nb < 4; nb++)
                ldsm4(bf[nb], swz(st + 32768, wn * 64 + nb * 16 + (lane & 15), acol));
            // pass 1: xH * wH  (all)
#pragma unroll
            for (int nb = 0; nb < 4; nb++) {
                uint32_t lo[2] = {bf[nb][0], bf[nb][2]}, hi[2] = {bf[nb][1], bf[nb][3]};
                mma_f16(acc[0][nb * 2], aH[0], lo); mma_f16(acc[0][nb * 2 + 1], aH[0], hi);
                mma_f16(acc[1][nb * 2], aH[1], lo); mma_f16(acc[1][nb * 2 + 1], aH[1], hi);
            }
            // pass 2: xL * wH  (Q, V)
            if (sel != 1) {
#pragma unroll
                for (int nb = 0; nb < 4; nb++) {
                    uint32_t lo[2] = {bf[nb][0], bf[nb][2]}, hi[2] = {bf[nb][1], bf[nb][3]};
                    mma_f16(acc[0][nb * 2], aL[0], lo); mma_f16(acc[0][nb * 2 + 1], aL[0], hi);
                    mma_f16(acc[1][nb * 2], aL[1], lo); mma_f16(acc[1][nb * 2 + 1], aL[1], hi);
                }
            }
            // pass 3: xH * wL  (Q only)
            if (sel == 0) {
#pragma unroll
                for (int nb = 0; nb < 4; nb++)
                    ldsm4(bf[nb], swz(st + 65536, wn * 64 + nb * 16 + (lane & 15), acol));
#pragma unroll
                for (int nb = 0; nb < 4; nb++) {
                    uint32_t lo[2] = {bf[nb][0], bf[nb][2]}, hi[2] = {bf[nb][1], bf[nb][3]};
                    mma_f16(acc[0][nb * 2], aH[0], lo); mma_f16(acc[0][nb * 2 + 1], aH[0], hi);
                    mma_f16(acc[1][nb * 2], aH[1], lo); mma_f16(acc[1][nb * 2 + 1], aH[1], hi);
                }
            }
        }
    }

    const float* bias = sel == 0 ? bq : (sel == 1 ? bk : bv);
#pragma unroll
    for (int mi = 0; mi < 2; mi++)
#pragma unroll
        for (int nf = 0; nf < 8; nf++) {
            int og = o0 + wn * 64 + nf * 8 + (lane & 3) * 2;
            float b0 = bias[og], b1 = bias[og + 1];
            int r0 = n0 + wm * 32 + mi * 16 + (lane >> 2);
            float v0 = acc[mi][nf][0] + b0, v1 = acc[mi][nf][1] + b1;
            float v2 = acc[mi][nf][2] + b0, v3 = acc[mi][nf][3] + b1;
            if (sel == 2) {
                __half* vp = g_v + ((size_t)b * C_ + og) * N_;
                vp[r0] = __float2half_rn(v0);
                vp[r0 + 8] = __float2half_rn(v2);
                vp[N_ + r0] = __float2half_rn(v1);
                vp[N_ + r0 + 8] = __float2half_rn(v3);
            } else if (sel == 1) {
                int hh = og >> 6, d = og & 63;
                __half* kp = g_k + (size_t)(b * H_ + hh) * N_ * DH;
                *(__half2*)&kp[(size_t)r0 * DH + d] =
                    __halves2half2(__float2half_rn(v0), __float2half_rn(v1));
                *(__half2*)&kp[(size_t)(r0 + 8) * DH + d] =
                    __halves2half2(__float2half_rn(v2), __float2half_rn(v3));
            } else {
                int hh = og >> 6, d = og & 63;
                __half* TH = g_qh + (size_t)(b * H_ + hh) * N_ * DH;
                __half* TL = g_ql + (size_t)(b * H_ + hh) * N_ * DH;
                __half h0, l0, h1, l1;
                split_h(v0, h0, l0); split_h(v1, h1, l1);
                *(__half2*)&TH[(size_t)r0 * DH + d] = __halves2half2(h0, h1);
                *(__half2*)&TL[(size_t)r0 * DH + d] = __halves2half2(l0, l1);
                split_h(v2, h0, l0); split_h(v3, h1, l1);
                *(__half2*)&TH[(size_t)(r0 + 8) * DH + d] = __halves2half2(h0, h1);
                *(__half2*)&TL[(size_t)(r0 + 8) * DH + d] = __halves2half2(l0, l1);
            }
        }
}

// ---------------- stage 1.5: U = rh^T q, W = rw^T q (per bh) --------------
#define SMEM_UW 65536
__global__ __launch_bounds__(256) void uw_mma() {
    extern __shared__ char smem[];
    uint32_t sb = s2u(smem);
    int t = threadIdx.x, lane = t & 31, wid = t >> 5;
    int wm = wid & 1, wn = wid >> 1;
    int m0 = blockIdx.x * 128;
    int bh = blockIdx.y, h = bh & 7;

#pragma unroll
    for (int pp = 0; pp < 2; pp++) {
        int idx = t + pp * 256;
        int row = idx >> 3, g = idx & 7;
        int off = h * 2048 + (row & 31) * 64 + g * 8;
        const __half* srcH = (row < 32 ? g_rhh : g_rwh) + off;
        const __half* srcL = (row < 32 ? g_rhl : g_rwl) + off;
        cpasync16(swz(sb, row, g), srcH);
        cpasync16(swz(sb + 8192, row, g), srcL);
    }
    const __half* QHp = g_qh + ((size_t)bh * N_ + m0) * DH;
    const __half* QLp = g_ql + ((size_t)bh * N_ + m0) * DH;
#pragma unroll
    for (int pp = 0; pp < 4; pp++) {
        int idx = t + pp * 256;
        int row = idx >> 3, g = idx & 7;
        cpasync16(swz(sb + 16384, row, g), QHp + (size_t)row * DH + g * 8);
        cpasync16(swz(sb + 32768, row, g), QLp + (size_t)row * DH + g * 8);
    }
    cp_commit();
    cp_wait0();
    __syncthreads();

    float acc[2][4][4];
#pragma unroll
    for (int i = 0; i < 2; i++)
#pragma unroll
        for (int j = 0; j < 4; j++)
#pragma unroll
            for (int k = 0; k < 4; k++) acc[i][j][k] = 0.f;

#pragma unroll
    for (int ks = 0; ks < 4; ks++) {
        int acol = 2 * ks + (lane >> 4);
        uint32_t aH[2][4], aL[2][4];
#pragma unroll
        for (int mi = 0; mi < 2; mi++) {
            int arow = wm * 32 + mi * 16 + (lane & 15);
            ldsm4(aH[mi], swz(sb, arow, acol));
            ldsm4(aL[mi], swz(sb + 8192, arow, acol));
        }
        uint32_t bH[2][4], bL[2][4];
#pragma unroll
        for (int nbb = 0; nbb < 2; nbb++) {
            int brow = wn * 32 + nbb * 16 + (lane & 15);
            ldsm4(bH[nbb], swz(sb + 16384, brow, acol));
            ldsm4(bL[nbb], swz(sb + 32768, brow, acol));
        }
#pragma unroll
        for (int nbb = 0; nbb < 2; nbb++) {
            uint32_t lo[2] = {bH[nbb][0], bH[nbb][2]}, hi[2] = {bH[nbb][1], bH[nbb][3]};
            mma_f16(acc[0][nbb * 2], aH[0], lo); mma_f16(acc[0][nbb * 2 + 1], aH[0], hi);
            mma_f16(acc[1][nbb * 2], aH[1], lo); mma_f16(acc[1][nbb * 2 + 1], aH[1], hi);
        }
#pragma unroll
        for (int nbb = 0; nbb < 2; nbb++) {
            uint32_t lo[2] = {bH[nbb][0], bH[nbb][2]}, hi[2] = {bH[nbb][1], bH[nbb][3]};
            mma_f16(acc[0][nbb * 2], aL[0], lo); mma_f16(acc[0][nbb * 2 + 1], aL[0], hi);
            mma_f16(acc[1][nbb * 2], aL[1], lo); mma_f16(acc[1][nbb * 2 + 1], aL[1], hi);
        }
#pragma unroll
        for (int nbb = 0; nbb < 2; nbb++) {
            uint32_t lo[2] = {bL[nbb][0], bL[nbb][2]}, hi[2] = {bL[nbb][1], bL[nbb][3]};
            mma_f16(acc[0][nbb * 2], aH[0], lo); mma_f16(acc[0][nbb * 2 + 1], aH[0], hi);
            mma_f16(acc[1][nbb * 2], aH[1], lo); mma_f16(acc[1][nbb * 2 + 1], aH[1], hi);
        }
    }

    float* base = wm == 0 ? g_U : g_W;
#pragma unroll
    for (int mi = 0; mi < 2; mi++)
#pragma unroll
        for (int nf = 0; nf < 4; nf++) {
            int rr = (mi * 16 + (lane >> 2)) & 31;
            int col = m0 + wn * 32 + nf * 8 + (lane & 3) * 2;
            float2 v0 = {acc[mi][nf][0], acc[mi][nf][1]};
            float2 v1 = {acc[mi][nf][2], acc[mi][nf][3]};
            *(float2*)&base[((size_t)bh * 32 + rr) * N_ + col] = v0;
            *(float2*)&base[((size_t)bh * 32 + rr + 8) * N_ + col] = v1;
        }
}

// ---------------- stage 2-4 fused flash attention ------------------------
// 256 thr = 8 warps, 64-query tiles, 2 CTAs/SM. Warp pair (w, w+4): same 16
// query rows, opposite 64-key halves. exp via ex2.approx.f16x2; row-sum l
// via ones-MMA. smem: QH 0..8K | KV 8K + p*32K | U 73728 | W 90624.
#define FA_KV 8192
#define FA_U 73728
#define FA_W 90624
#define SMEM_FU 91712
__global__ __launch_bounds__(256, 2) void attn_fused(float* __restrict__ out) {
    extern __shared__ char smem[];
    uint32_t sb = s2u(smem);
    int t = threadIdx.x, lane = t & 31, w = t >> 5;
    int wq4 = w & 3;          // query-row group (16 rows each)
    int hv = w >> 2;          // key half: 0 or 1
    int q0 = blockIdx.x * 64;
    int bh = blockIdx.y, b = bh >> 3, h = bh & 7;

    const __half* QH = g_qh + (size_t)bh * N_ * DH;
    const __half* K  = g_k + (size_t)bh * N_ * DH;
    const __half* V  = g_v + (size_t)(b * C_ + h * DH) * N_;   // [64][1024]
    const float*  Ug = g_U + (size_t)bh * 32 * N_;
    const float*  Wg = g_W + ((size_t)bh * 32 + (q0 >> 5)) * N_;

    // QH rows q0..q0+63
    {
#pragma unroll
        for (int p = 0; p < 2; p++) {
            int idx = t + p * 256;
            int row = idx >> 3, g = idx & 7;
            cpasync16(swz(sb, row, g), QH + (size_t)(q0 + row) * DH + g * 8);
        }
        cp_commit();
    }

    auto prefetch_kv = [&](int j, int p) {
        int n0 = j * 128;
        uint32_t bb = sb + FA_KV + p * 32768;
#pragma unroll
        for (int pp = 0; pp < 4; pp++) {
            int idx = t + pp * 256;
            int row = idx >> 3, g = idx & 7;
            cpasync16(swz(bb, row, g), K + (size_t)(n0 + row) * DH + g * 8);
        }
#pragma unroll
        for (int pp = 0; pp < 4; pp++) {
            int idx = t + pp * 256;
            int row = idx >> 4, g = idx & 15;   // V [64][128] tile
            cpasync16(swzv(bb + 16384, row, g), V + (size_t)row * N_ + n0 + g * 8);
        }
        cp_commit();
    };
    auto prefetch_uw = [&](int j) {
        int n0 = j * 128;
#pragma unroll
        for (int pp = 0; pp < 4; pp++) {
            int idx = t + pp * 256;
            int row = idx >> 5, g = idx & 31;   // U: 32 rows (528B rows)
            cpasync16(sb + FA_U + row * 528 + g * 16, Ug + (size_t)row * N_ + n0 + g * 4);
        }
        if (t < 64) {
            int row = t >> 5, g = t & 31;       // W: 2 rows
            cpasync16(sb + FA_W + row * 528 + g * 16, Wg + (size_t)row * N_ + n0 + g * 4);
        }
        cp_commit();
    };

    prefetch_kv(0, 0);
    prefetch_uw(0);

    int rbase = wq4 * 16 + (lane >> 2);          // 0..63
    int i0 = rbase & 31, i1 = (rbase + 8) & 31;
    int jl0 = rbase >> 5, jl1 = (rbase + 8) >> 5;

    const float L2E = 1.4426950408889634f;
    const uint32_t ONES2 = 0x3C003C00u;          // fp16 {1, 1}
    uint32_t onesb[2] = {ONES2, ONES2};

    float m0 = -1e30f, m1 = -1e30f;
    float lacc[4] = {0.f, 0.f, 0.f, 0.f};
    float y[8][4];
#pragma unroll
    for (int i = 0; i < 8; i++)
#pragma unroll
        for (int j = 0; j < 4; j++) y[i][j] = 0.f;

    for (int j = 0; j < 8; j++) {
        cp_wait0();
        __syncthreads();
        int p = j & 1;
        if (j < 7) prefetch_kv(j + 1, p ^ 1);
        uint32_t bb = sb + FA_KV + p * 32768;

        // ---- scores: single term qh·k, 16 q rows x 64-key half ----
        float s[8][4];
#pragma unroll
        for (int f = 0; f < 8; f++)
#pragma unroll
            for (int k = 0; k < 4; k++) s[f][k] = 0.f;

#pragma unroll
        for (int ks = 0; ks < 4; ks++) {
            int arow = wq4 * 16 + (lane & 15), acol = 2 * ks + (lane >> 4);
            uint32_t aQH[4];
            ldsm4(aQH, swz(sb, arow, acol));
            uint32_t bf[4][4];
#pragma unroll
            for (int nb = 0; nb < 4; nb++)
                ldsm4(bf[nb], swz(bb, hv * 64 + nb * 16 + (lane & 15), acol));
#pragma unroll
            for (int nb = 0; nb < 4; nb++) {
                uint32_t lo[2] = {bf[nb][0], bf[nb][2]}, hi[2] = {bf[nb][1], bf[nb][3]};
                mma_f16(s[nb * 2], aQH, lo); mma_f16(s[nb * 2 + 1], aQH, hi);
            }
        }

        // ---- add positional term from staged U/W (single buffer) ----
#pragma unroll
        for (int nb = 0; nb < 4; nb++)
#pragma unroll
            for (int half = 0; half < 2; half++) {
                int col = hv * 64 + nb * 16 + half * 8 + (lane & 3) * 2;
                float2 u0 = *(const float2*)(smem + FA_U + i0 * 528 + col * 4);
                float2 u1 = *(const float2*)(smem + FA_U + i1 * 528 + col * 4);
                float2 w0 = *(const float2*)(smem + FA_W + jl0 * 528 + col * 4);
                float2 w1 = *(const float2*)(smem + FA_W + jl1 * 528 + col * 4);
                int f = nb * 2 + half;
                s[f][0] += u0.x + w0.x;
                s[f][1] += u0.y + w0.y;
                s[f][2] += u1.x + w1.x;
                s[f][3] += u1.y + w1.y;
            }
        __syncthreads();                  // all warps done with U/W(j)
        if (j < 7) prefetch_uw(j + 1);    // overwrite U/W with next tile

        // ---- per-warp online softmax (its key half only) ----
        float tmax0 = -1e30f, tmax1 = -1e30f;
#pragma unroll
        for (int f = 0; f < 8; f++) {
            tmax0 = fmaxf(tmax0, fmaxf(s[f][0], s[f][1]));
            tmax1 = fmaxf(tmax1, fmaxf(s[f][2], s[f][3]));
        }
        tmax0 = fmaxf(tmax0, __shfl_xor_sync(0xffffffffu, tmax0, 1));
        tmax0 = fmaxf(tmax0, __shfl_xor_sync(0xffffffffu, tmax0, 2));
        tmax1 = fmaxf(tmax1, __shfl_xor_sync(0xffffffffu, tmax1, 1));
        tmax1 = fmaxf(tmax1, __shfl_xor_sync(0xffffffffu, tmax1, 2));
        float mn0 = fmaxf(m0, tmax0), mn1 = fmaxf(m1, tmax1);
        float sc0 = __expf(m0 - mn0), sc1 = __expf(m1 - mn1);
        m0 = mn0; m1 = mn1;

        // p = 2^((s - mn) * log2e) via fp16x2 MUFU (2 weights per op)
        float b0s = mn0 * L2E, b1s = mn1 * L2E;
        uint32_t pf[8][2];
#pragma unroll
        for (int f = 0; f < 8; f++) {
            float e0 = fmaf(s[f][0], L2E, -b0s);
            float e1 = fmaf(s[f][1], L2E, -b0s);
            float e2 = fmaf(s[f][2], L2E, -b1s);
            float e3 = fmaf(s[f][3], L2E, -b1s);
            pf[f][0] = ex2h2(cvt2h(e1, e0));
            pf[f][1] = ex2h2(cvt2h(e3, e2));
        }
        lacc[0] *= sc0; lacc[1] *= sc0;
        lacc[2] *= sc1; lacc[3] *= sc1;
#pragma unroll
        for (int nf = 0; nf < 8; nf++) {
            y[nf][0] *= sc0; y[nf][1] *= sc0;
            y[nf][2] *= sc1; y[nf][3] *= sc1;
        }

        // ---- y += P @ V^T; l += P @ ones  (this warp's 64 keys) ----
#pragma unroll
        for (int ks = 0; ks < 4; ks++) {
            uint32_t a[4] = {pf[2 * ks][0], pf[2 * ks][1], pf[2 * ks + 1][0], pf[2 * ks + 1][1]};
            int vcol = hv * 8 + 2 * ks + (lane >> 4);
            mma_f16(lacc, a, onesb);
#pragma unroll
            for (int nb = 0; nb < 4; nb++) {
                uint32_t bf[4];
                ldsm4(bf, swzv(bb + 16384, nb * 16 + (lane & 15), vcol));
                uint32_t blo[2] = {bf[0], bf[2]}, bhi[2] = {bf[1], bf[3]};
                mma_f16(y[nb * 2], a, blo);
                mma_f16(y[nb * 2 + 1], a, bhi);
            }
        }
    }

    float l0 = lacc[0], l1 = lacc[2];

    // ---- epilogue: pairwise flash merge via smem, then store ----
    __syncthreads();   // KV/U region now free
    float* yst = (float*)(smem + FA_KV);            // [64 d][68 q] = 17408 B
    float* yb = (float*)(smem + FA_KV + 17408);     // [64 q][68 d] = 17408 B
    float* mb = (float*)(smem + FA_KV + 34816);     // 64 f32
    float* lb = mb + 64;
    int rl = rbase;

    if (hv == 1) {
#pragma unroll
        for (int nf = 0; nf < 8; nf++) {
            int d0 = nf * 8 + (lane & 3) * 2;
            yb[rl * 68 + d0] = y[nf][0];
            yb[rl * 68 + d0 + 1] = y[nf][1];
            yb[(rl + 8) * 68 + d0] = y[nf][2];
            yb[(rl + 8) * 68 + d0 + 1] = y[nf][3];
        }
        if ((lane & 3) == 0) {
            mb[rl] = m0; lb[rl] = l0;
            mb[rl + 8] = m1; lb[rl + 8] = l1;
        }
    }
    __syncthreads();

    if (hv == 0) {
        float mB0 = mb[rl], lB0 = lb[rl], mB1 = mb[rl + 8], lB1 = lb[rl + 8];
        float mf0 = fmaxf(m0, mB0), mf1 = fmaxf(m1, mB1);
        float fa0 = __expf(m0 - mf0), fb0 = __expf(mB0 - mf0);
        float fa1 = __expf(m1 - mf1), fb1 = __expf(mB1 - mf1);
        float inv0 = 1.f / (l0 * fa0 + lB0 * fb0);
        float inv1 = 1.f / (l1 * fa1 + lB1 * fb1);
        float sa0 = fa0 * inv0, sb0 = fb0 * inv0;
        float sa1 = fa1 * inv1, sb1 = fb1 * inv1;
#pragma unroll
        for (int nf = 0; nf < 8; nf++) {
            int d0 = nf * 8 + (lane & 3) * 2;
            yst[d0 * 68 + rl]       = y[nf][0] * sa0 + yb[rl * 68 + d0] * sb0;
            yst[(d0 + 1) * 68 + rl] = y[nf][1] * sa0 + yb[rl * 68 + d0 + 1] * sb0;
            yst[d0 * 68 + rl + 8]       = y[nf][2] * sa1 + yb[(rl + 8) * 68 + d0] * sb1;
            yst[(d0 + 1) * 68 + rl + 8] = y[nf][3] * sa1 + yb[(rl + 8) * 68 + d0 + 1] * sb1;
        }
    }
    __syncthreads();
    float* O = out + (size_t)(b * C_ + h * DH) * N_ + q0;
    for (int i = t; i < 1024; i += 256) {
        int d = i >> 4, qg = i & 15;
        float4 vv = *(float4*)&yst[d * 68 + qg * 4];
        *(float4*)&O[(size_t)d * N_ + qg * 4] = vv;
    }
}

// ---------------- launch ----------------
extern "C" void kernel_launch(void* const* d_in, const int* in_sizes, int n_in,
                              void* d_out, int out_size) {
    const float* x  = (const float*)d_in[0];
    const float* wq = (const float*)d_in[1];
    const float* bq = (const float*)d_in[2];
    const float* wk = (const float*)d_in[3];
    const float* bk = (const float*)d_in[4];
    const float* wv = (const float*)d_in[5];
    const float* bv = (const float*)d_in[6];
    const float* rh = (const float*)d_in[7];
    const float* rw = (const float*)d_in[8];

    cudaFuncSetAttribute(qkv_mma, cudaFuncAttributeMaxDynamicSharedMemorySize, SMEM_QKV);
    cudaFuncSetAttribute(uw_mma, cudaFuncAttributeMaxDynamicSharedMemorySize, SMEM_UW);
    cudaFuncSetAttribute(attn_fused, cudaFuncAttributeMaxDynamicSharedMemorySize, SMEM_FU);

    prep_w<<<(3 * C_ * C_) / 256, 256>>>(wq, wk, wv);
    prep_xt<<<dim3(N_ / 32, C_ / 32, B_), dim3(32, 32)>>>(x);
    prep_r<<<H_ * 32 * DH / 256, 256>>>(rh, rw);

    qkv_mma<<<dim3(8, 2, 24), 512, SMEM_QKV>>>(bq, bk, bv);
    uw_mma<<<dim3(8, BH_), 256, SMEM_UW>>>();
    attn_fused<<<dim3(16, BH_), 256, SMEM_FU>>>((float*)d_out);
}

// round 14
// speedup vs baseline: 1.1907x; 1.0335x over previous
#include <cuda_runtime.h>
#include <cuda_fp16.h>
#include <cstdint>

#define B_  8
#define C_  512
#define H_  8
#define DH  64
#define N_  1024
#define BH_ 64

// ---------------- scratch (__device__ globals; no allocs) ----------------
__device__ __half g_Wh[3 * C_ * C_], g_Wl[3 * C_ * C_];          // [sel][o][c]
__device__ __half g_XTh[B_ * N_ * C_], g_XTl[B_ * N_ * C_];      // [b][n][c]
__device__ __half g_rhh[H_ * 32 * DH], g_rhl[H_ * 32 * DH];      // [h][i][d] (rh^T)
__device__ __half g_rwh[H_ * 32 * DH], g_rwl[H_ * 32 * DH];      // [h][j][d] (rw^T)
__device__ __half g_qh[BH_ * N_ * DH], g_ql[BH_ * N_ * DH];      // [bh][n][d]
__device__ __half g_k[BH_ * N_ * DH];                            // [bh][n][d] single fp16
__device__ __half g_v[(size_t)B_ * C_ * N_];                     // [b][c][n]
__device__ float  g_U[(size_t)BH_ * 32 * N_];                    // [bh][i][m]
__device__ float  g_W[(size_t)BH_ * 32 * N_];                    // [bh][j][m]

// ---------------- helpers ----------------
__device__ __forceinline__ uint32_t s2u(const void* p) {
    uint32_t a;
    asm("{ .reg .u64 t; cvta.to.shared.u64 t, %1; cvt.u32.u64 %0, t; }" : "=r"(a) : "l"(p));
    return a;
}
__device__ __forceinline__ void cpasync16(uint32_t dst, const void* src) {
    asm volatile("cp.async.ca.shared.global [%0], [%1], 16;" :: "r"(dst), "l"(src));
}
__device__ __forceinline__ void cp_commit() {
    asm volatile("cp.async.commit_group;" ::: "memory");
}
__device__ __forceinline__ void cp_wait0() {
    asm volatile("cp.async.wait_group 0;" ::: "memory");
}
__device__ __forceinline__ void ldsm4(uint32_t* r, uint32_t addr) {
    asm volatile("ldmatrix.sync.aligned.m8n8.x4.shared.b16 {%0,%1,%2,%3}, [%4];"
                 : "=r"(r[0]), "=r"(r[1]), "=r"(r[2]), "=r"(r[3]) : "r"(addr));
}
__device__ __forceinline__ void mma_f16(float* c, const uint32_t* a, const uint32_t* b) {
    asm volatile(
        "mma.sync.aligned.m16n8k16.row.col.f32.f16.f16.f32 "
        "{%0,%1,%2,%3},{%4,%5,%6,%7},{%8,%9},{%0,%1,%2,%3};"
        : "+f"(c[0]), "+f"(c[1]), "+f"(c[2]), "+f"(c[3])
        : "r"(a[0]), "r"(a[1]), "r"(a[2]), "r"(a[3]), "r"(b[0]), "r"(b[1]));
}
// 128B-row tiles ([rows][64] half), XOR swizzle on 16B granules
__device__ __forceinline__ uint32_t swz(uint32_t base, int row, int g) {
    return base + row * 128 + ((g ^ (row & 7)) << 4);
}
// 256B-row tiles ([rows][128] half)
__device__ __forceinline__ uint32_t swzv(uint32_t base, int row, int g) {
    return base + row * 256 + ((g ^ (row & 7)) << 4);
}
__device__ __forceinline__ void split_h(float a, __half& h, __half& l) {
    h = __float2half_rn(a);
    l = __float2half_rn(a - __half2float(h));
}
__device__ __forceinline__ uint32_t cvt2h(float hi, float lo) {
    uint32_t r;
    asm("cvt.rn.f16x2.f32 %0, %1, %2;" : "=r"(r) : "f"(hi), "f"(lo));
    return r;
}
__device__ __forceinline__ uint32_t ex2h2(uint32_t x) {
    uint32_t r;
    asm("ex2.approx.f16x2 %0, %1;" : "=r"(r) : "r"(x));
    return r;
}

// ---------------- merged prep kernel ----------------
// blocks [0, 3072): W split.  [3072, 3136): rh/rw transpose+split.
// [3136, 7232): x transpose+split (4096 tiles of 32x32, 256 thr).
__global__ __launch_bounds__(256) void prep_all(
    const float* __restrict__ wq, const float* __restrict__ wk,
    const float* __restrict__ wv, const float* __restrict__ rh,
    const float* __restrict__ rw, const float* __restrict__ x) {
    __shared__ float sm[32][33];
    int blk = blockIdx.x, t = threadIdx.x;
    if (blk < 3072) {
        int idx = blk * 256 + t;
        int sel = idx >> 18, rc = idx & 262143;
        const float* W = sel == 0 ? wq : (sel == 1 ? wk : wv);
        __half h, l;
        split_h(W[rc], h, l);
        g_Wh[idx] = h; g_Wl[idx] = l;
    } else if (blk < 3136) {
        int idx = (blk - 3072) * 256 + t;   // [h][i][d], 16384 total
        int h = idx >> 11, i = (idx >> 6) & 31, d = idx & 63;
        __half hh, ll;
        split_h(rh[(h * DH + d) * 32 + i], hh, ll);
        g_rhh[idx] = hh; g_rhl[idx] = ll;
        split_h(rw[(h * DH + d) * 32 + i], hh, ll);
        g_rwh[idx] = hh; g_rwl[idx] = ll;
    } else {
        int blk2 = blk - 3136;
        int b = blk2 >> 9;
        int rem = blk2 & 511;
        int c0 = (rem >> 5) * 32, n0 = (rem & 31) * 32;
#pragma unroll
        for (int i = 0; i < 4; i++) {
            int e = t + i * 256;
            int r = e >> 5, cn = e & 31;
            sm[r][cn] = x[((size_t)b * C_ + c0 + r) * N_ + n0 + cn];
        }
        __syncthreads();
#pragma unroll
        for (int i = 0; i < 4; i++) {
            int e = t + i * 256;
            int r = e >> 5, cn = e & 31;
            __half h, l;
            split_h(sm[cn][r], h, l);
            size_t off = ((size_t)b * N_ + n0 + r) * C_ + c0 + cn;
            g_XTh[off] = h; g_XTl[off] = l;
        }
    }
}

// ---------------- stage 1: QKV projection (mma.sync, hi/lo) --------------
// CTA tile 128n x 256o, 512 thr = 16 warps (4 wm x 4 wn), warp tile 32x64.
// Q: 3 terms; V: 2 terms; K: 1 term. LPT dispatch order: Q, V, K.
#define QKV_STG 98304
#define SMEM_QKV 196608
__global__ __launch_bounds__(512) void qkv_mma(const float* __restrict__ bq,
                                               const float* __restrict__ bk,
                                               const float* __restrict__ bv) {
    extern __shared__ char smem[];
    uint32_t sb = s2u(smem);
    int t = threadIdx.x, lane = t & 31, wid = t >> 5;
    int wm = wid & 3, wn = wid >> 2;
    int n0 = blockIdx.x * 128, o0 = blockIdx.y * 256;
    int z = blockIdx.z;
    int order = z >> 3, b = z & 7;
    int sel = order == 0 ? 0 : (order == 1 ? 2 : 1);   // Q, V, K (LPT)

    const __half* XH = g_XTh + (size_t)b * N_ * C_ + (size_t)n0 * C_;
    const __half* XL = g_XTl + (size_t)b * N_ * C_ + (size_t)n0 * C_;
    const __half* WH = g_Wh + (size_t)sel * C_ * C_ + (size_t)o0 * C_;
    const __half* WL = g_Wl + (size_t)sel * C_ * C_ + (size_t)o0 * C_;

    float acc[2][8][4];
#pragma unroll
    for (int i = 0; i < 2; i++)
#pragma unroll
        for (int j = 0; j < 8; j++)
#pragma unroll
            for (int k = 0; k < 4; k++) acc[i][j][k] = 0.f;

    auto issue = [&](int cc, int buf) {
        uint32_t st = sb + buf * QKV_STG;
#pragma unroll
        for (int i = 0; i < 4; i++) {
            int idx = t + i * 512;
            int which = idx >> 10, r = (idx & 1023) >> 3, g = idx & 7;
            if (which == 1 && sel == 1) continue;          // K: no XL
            const __half* src = (which ? XL : XH) + cc * 64 + (size_t)r * C_ + g * 8;
            cpasync16(swz(st + which * 16384, r, g), src);
        }
#pragma unroll
        for (int i = 0; i < 8; i++) {
            int idx = t + i * 512;
            int which = idx >> 11, r = (idx & 2047) >> 3, g = idx & 7;
            if (which == 1 && sel != 0) continue;          // K,V: no WL
            const __half* src = (which ? WL : WH) + cc * 64 + (size_t)r * C_ + g * 8;
            cpasync16(swz(st + 32768 + which * 32768, r, g), src);
        }
        cp_commit();
    };

    issue(0, 0);
    for (int cc = 0; cc < 8; cc++) {
        cp_wait0();
        __syncthreads();
        if (cc < 7) issue(cc + 1, (cc + 1) & 1);
        uint32_t st = sb + (cc & 1) * QKV_STG;
#pragma unroll
        for (int ks = 0; ks < 4; ks++) {
            int acol = 2 * ks + (lane >> 4);
            uint32_t aH[2][4], aL[2][4];
#pragma unroll
            for (int mi = 0; mi < 2; mi++) {
                int arow = wm * 32 + mi * 16 + (lane & 15);
                ldsm4(aH[mi], swz(st, arow, acol));
                if (sel != 1)
                    ldsm4(aL[mi], swz(st + 16384, arow, acol));
            }
            uint32_t bf[4][4];
#pragma unroll
            for (int nb = 0; nb < 4; nb++)
                ldsm4(bf[nb], swz(st + 32768, wn * 64 + nb * 16 + (lane & 15), acol));
            // pass 1: xH * wH  (all)
#pragma unroll
            for (int nb = 0; nb < 4; nb++) {
                uint32_t lo[2] = {bf[nb][0], bf[nb][2]}, hi[2] = {bf[nb][1], bf[nb][3]};
                mma_f16(acc[0][nb * 2], aH[0], lo); mma_f16(acc[0][nb * 2 + 1], aH[0], hi);
                mma_f16(acc[1][nb * 2], aH[1], lo); mma_f16(acc[1][nb * 2 + 1], aH[1], hi);
            }
            // pass 2: xL * wH  (Q, V)
            if (sel != 1) {
#pragma unroll
                for (int nb = 0; nb < 4; nb++) {
                    uint32_t lo[2] = {bf[nb][0], bf[nb][2]}, hi[2] = {bf[nb][1], bf[nb][3]};
                    mma_f16(acc[0][nb * 2], aL[0], lo); mma_f16(acc[0][nb * 2 + 1], aL[0], hi);
                    mma_f16(acc[1][nb * 2], aL[1], lo); mma_f16(acc[1][nb * 2 + 1], aL[1], hi);
                }
            }
            // pass 3: xH * wL  (Q only)
            if (sel == 0) {
#pragma unroll
                for (int nb = 0; nb < 4; nb++)
                    ldsm4(bf[nb], swz(st + 65536, wn * 64 + nb * 16 + (lane & 15), acol));
#pragma unroll
                for (int nb = 0; nb < 4; nb++) {
                    uint32_t lo[2] = {bf[nb][0], bf[nb][2]}, hi[2] = {bf[nb][1], bf[nb][3]};
                    mma_f16(acc[0][nb * 2], aH[0], lo); mma_f16(acc[0][nb * 2 + 1], aH[0], hi);
                    mma_f16(acc[1][nb * 2], aH[1], lo); mma_f16(acc[1][nb * 2 + 1], aH[1], hi);
                }
            }
        }
    }

    const float* bias = sel == 0 ? bq : (sel == 1 ? bk : bv);
#pragma unroll
    for (int mi = 0; mi < 2; mi++)
#pragma unroll
        for (int nf = 0; nf < 8; nf++) {
            int og = o0 + wn * 64 + nf * 8 + (lane & 3) * 2;
            float b0 = bias[og], b1 = bias[og + 1];
            int r0 = n0 + wm * 32 + mi * 16 + (lane >> 2);
            float v0 = acc[mi][nf][0] + b0, v1 = acc[mi][nf][1] + b1;
            float v2 = acc[mi][nf][2] + b0, v3 = acc[mi][nf][3] + b1;
            if (sel == 2) {
                __half* vp = g_v + ((size_t)b * C_ + og) * N_;
                vp[r0] = __float2half_rn(v0);
                vp[r0 + 8] = __float2half_rn(v2);
                vp[N_ + r0] = __float2half_rn(v1);
                vp[N_ + r0 + 8] = __float2half_rn(v3);
            } else if (sel == 1) {
                int hh = og >> 6, d = og & 63;
                __half* kp = g_k + (size_t)(b * H_ + hh) * N_ * DH;
                *(__half2*)&kp[(size_t)r0 * DH + d] =
                    __halves2half2(__float2half_rn(v0), __float2half_rn(v1));
                *(__half2*)&kp[(size_t)(r0 + 8) * DH + d] =
                    __halves2half2(__float2half_rn(v2), __float2half_rn(v3));
            } else {
                int hh = og >> 6, d = og & 63;
                __half* TH = g_qh + (size_t)(b * H_ + hh) * N_ * DH;
                __half* TL = g_ql + (size_t)(b * H_ + hh) * N_ * DH;
                __half h0, l0, h1, l1;
                split_h(v0, h0, l0); split_h(v1, h1, l1);
                *(__half2*)&TH[(size_t)r0 * DH + d] = __halves2half2(h0, h1);
                *(__half2*)&TL[(size_t)r0 * DH + d] = __halves2half2(l0, l1);
                split_h(v2, h0, l0); split_h(v3, h1, l1);
                *(__half2*)&TH[(size_t)(r0 + 8) * DH + d] = __halves2half2(h0, h1);
                *(__half2*)&TL[(size_t)(r0 + 8) * DH + d] = __halves2half2(l0, l1);
            }
        }
}

// ---------------- stage 1.5: U = rh^T q, W = rw^T q (per bh) --------------
#define SMEM_UW 65536
__global__ __launch_bounds__(256) void uw_mma() {
    extern __shared__ char smem[];
    uint32_t sb = s2u(smem);
    int t = threadIdx.x, lane = t & 31, wid = t >> 5;
    int wm = wid & 1, wn = wid >> 1;
    int m0 = blockIdx.x * 128;
    int bh = blockIdx.y, h = bh & 7;

#pragma unroll
    for (int pp = 0; pp < 2; pp++) {
        int idx = t + pp * 256;
        int row = idx >> 3, g = idx & 7;
        int off = h * 2048 + (row & 31) * 64 + g * 8;
        const __half* srcH = (row < 32 ? g_rhh : g_rwh) + off;
        const __half* srcL = (row < 32 ? g_rhl : g_rwl) + off;
        cpasync16(swz(sb, row, g), srcH);
        cpasync16(swz(sb + 8192, row, g), srcL);
    }
    const __half* QHp = g_qh + ((size_t)bh * N_ + m0) * DH;
    const __half* QLp = g_ql + ((size_t)bh * N_ + m0) * DH;
#pragma unroll
    for (int pp = 0; pp < 4; pp++) {
        int idx = t + pp * 256;
        int row = idx >> 3, g = idx & 7;
        cpasync16(swz(sb + 16384, row, g), QHp + (size_t)row * DH + g * 8);
        cpasync16(swz(sb + 32768, row, g), QLp + (size_t)row * DH + g * 8);
    }
    cp_commit();
    cp_wait0();
    __syncthreads();

    float acc[2][4][4];
#pragma unroll
    for (int i = 0; i < 2; i++)
#pragma unroll
        for (int j = 0; j < 4; j++)
#pragma unroll
            for (int k = 0; k < 4; k++) acc[i][j][k] = 0.f;

#pragma unroll
    for (int ks = 0; ks < 4; ks++) {
        int acol = 2 * ks + (lane >> 4);
        uint32_t aH[2][4], aL[2][4];
#pragma unroll
        for (int mi = 0; mi < 2; mi++) {
            int arow = wm * 32 + mi * 16 + (lane & 15);
            ldsm4(aH[mi], swz(sb, arow, acol));
            ldsm4(aL[mi], swz(sb + 8192, arow, acol));
        }
        uint32_t bH[2][4], bL[2][4];
#pragma unroll
        for (int nbb = 0; nbb < 2; nbb++) {
            int brow = wn * 32 + nbb * 16 + (lane & 15);
            ldsm4(bH[nbb], swz(sb + 16384, brow, acol));
            ldsm4(bL[nbb], swz(sb + 32768, brow, acol));
        }
#pragma unroll
        for (int nbb = 0; nbb < 2; nbb++) {
            uint32_t lo[2] = {bH[nbb][0], bH[nbb][2]}, hi[2] = {bH[nbb][1], bH[nbb][3]};
            mma_f16(acc[0][nbb * 2], aH[0], lo); mma_f16(acc[0][nbb * 2 + 1], aH[0], hi);
            mma_f16(acc[1][nbb * 2], aH[1], lo); mma_f16(acc[1][nbb * 2 + 1], aH[1], hi);
        }
#pragma unroll
        for (int nbb = 0; nbb < 2; nbb++) {
            uint32_t lo[2] = {bH[nbb][0], bH[nbb][2]}, hi[2] = {bH[nbb][1], bH[nbb][3]};
            mma_f16(acc[0][nbb * 2], aL[0], lo); mma_f16(acc[0][nbb * 2 + 1], aL[0], hi);
            mma_f16(acc[1][nbb * 2], aL[1], lo); mma_f16(acc[1][nbb * 2 + 1], aL[1], hi);
        }
#pragma unroll
        for (int nbb = 0; nbb < 2; nbb++) {
            uint32_t lo[2] = {bL[nbb][0], bL[nbb][2]}, hi[2] = {bL[nbb][1], bL[nbb][3]};
            mma_f16(acc[0][nbb * 2], aH[0], lo); mma_f16(acc[0][nbb * 2 + 1], aH[0], hi);
            mma_f16(acc[1][nbb * 2], aH[1], lo); mma_f16(acc[1][nbb * 2 + 1], aH[1], hi);
        }
    }

    float* base = wm == 0 ? g_U : g_W;
#pragma unroll
    for (int mi = 0; mi < 2; mi++)
#pragma unroll
        for (int nf = 0; nf < 4; nf++) {
            int rr = (mi * 16 + (lane >> 2)) & 31;
            int col = m0 + wn * 32 + nf * 8 + (lane & 3) * 2;
            float2 v0 = {acc[mi][nf][0], acc[mi][nf][1]};
            float2 v1 = {acc[mi][nf][2], acc[mi][nf][3]};
            *(float2*)&base[((size_t)bh * 32 + rr) * N_ + col] = v0;
            *(float2*)&base[((size_t)bh * 32 + rr + 8) * N_ + col] = v1;
        }
}

// ---------------- stage 2-4 fused flash attention ------------------------
// 256 thr = 8 warps, 64-query tiles, 2 CTAs/SM. Warp pair (w, w+4): same 16
// query rows, opposite 64-key halves. exp via ex2.approx.f16x2; row-sum l
// via ones-MMA. K/V AND U/W double-buffered -> one sync per key-tile.
// smem: QH 0..8K | KV 8192 + p*32768 | UW 73728 + p*19008 (U +0, W +16896).
#define FA_KV 8192
#define FA_UW 73728
#define UW_STRIDE 19008
#define SMEM_FU 111744
__global__ __launch_bounds__(256, 2) void attn_fused(float* __restrict__ out) {
    extern __shared__ char smem[];
    uint32_t sb = s2u(smem);
    int t = threadIdx.x, lane = t & 31, w = t >> 5;
    int wq4 = w & 3;          // query-row group (16 rows each)
    int hv = w >> 2;          // key half: 0 or 1
    int q0 = blockIdx.x * 64;
    int bh = blockIdx.y, b = bh >> 3, h = bh & 7;

    const __half* QH = g_qh + (size_t)bh * N_ * DH;
    const __half* K  = g_k + (size_t)bh * N_ * DH;
    const __half* V  = g_v + (size_t)(b * C_ + h * DH) * N_;   // [64][1024]
    const float*  Ug = g_U + (size_t)bh * 32 * N_;
    const float*  Wg = g_W + ((size_t)bh * 32 + (q0 >> 5)) * N_;

    // QH rows q0..q0+63
    {
#pragma unroll
        for (int p = 0; p < 2; p++) {
            int idx = t + p * 256;
            int row = idx >> 3, g = idx & 7;
            cpasync16(swz(sb, row, g), QH + (size_t)(q0 + row) * DH + g * 8);
        }
        cp_commit();
    }

    auto prefetch = [&](int j, int p) {
        int n0 = j * 128;
        uint32_t bb = sb + FA_KV + p * 32768;
#pragma unroll
        for (int pp = 0; pp < 4; pp++) {
            int idx = t + pp * 256;
            int row = idx >> 3, g = idx & 7;
            cpasync16(swz(bb, row, g), K + (size_t)(n0 + row) * DH + g * 8);
        }
#pragma unroll
        for (int pp = 0; pp < 4; pp++) {
            int idx = t + pp * 256;
            int row = idx >> 4, g = idx & 15;   // V [64][128] tile
            cpasync16(swzv(bb + 16384, row, g), V + (size_t)row * N_ + n0 + g * 8);
        }
        uint32_t uw = sb + FA_UW + p * UW_STRIDE;
#pragma unroll
        for (int pp = 0; pp < 4; pp++) {
            int idx = t + pp * 256;
            int row = idx >> 5, g = idx & 31;   // U: 32 rows (528B rows)
            cpasync16(uw + row * 528 + g * 16, Ug + (size_t)row * N_ + n0 + g * 4);
        }
        if (t < 64) {
            int row = t >> 5, g = t & 31;       // W: 2 rows
            cpasync16(uw + 16896 + row * 528 + g * 16, Wg + (size_t)row * N_ + n0 + g * 4);
        }
        cp_commit();
    };

    prefetch(0, 0);

    int rbase = wq4 * 16 + (lane >> 2);          // 0..63
    int i0 = rbase & 31, i1 = (rbase + 8) & 31;
    int jl0 = rbase >> 5, jl1 = (rbase + 8) >> 5;

    const float L2E = 1.4426950408889634f;
    const uint32_t ONES2 = 0x3C003C00u;          // fp16 {1, 1}
    uint32_t onesb[2] = {ONES2, ONES2};

    float m0 = -1e30f, m1 = -1e30f;
    float lacc[4] = {0.f, 0.f, 0.f, 0.f};
    float y[8][4];
#pragma unroll
    for (int i = 0; i < 8; i++)
#pragma unroll
        for (int j = 0; j < 4; j++) y[i][j] = 0.f;

    for (int j = 0; j < 8; j++) {
        cp_wait0();
        __syncthreads();
        int p = j & 1;
        if (j < 7) prefetch(j + 1, p ^ 1);
        uint32_t bb = sb + FA_KV + p * 32768;
        const char* uwc = smem + FA_UW + p * UW_STRIDE;

        // ---- scores: single term qh·k, 16 q rows x 64-key half ----
        float s[8][4];
#pragma unroll
        for (int f = 0; f < 8; f++)
#pragma unroll
            for (int k = 0; k < 4; k++) s[f][k] = 0.f;

#pragma unroll
        for (int ks = 0; ks < 4; ks++) {
            int arow = wq4 * 16 + (lane & 15), acol = 2 * ks + (lane >> 4);
            uint32_t aQH[4];
            ldsm4(aQH, swz(sb, arow, acol));
            uint32_t bf[4][4];
#pragma unroll
            for (int nb = 0; nb < 4; nb++)
                ldsm4(bf[nb], swz(bb, hv * 64 + nb * 16 + (lane & 15), acol));
#pragma unroll
            for (int nb = 0; nb < 4; nb++) {
                uint32_t lo[2] = {bf[nb][0], bf[nb][2]}, hi[2] = {bf[nb][1], bf[nb][3]};
                mma_f16(s[nb * 2], aQH, lo); mma_f16(s[nb * 2 + 1], aQH, hi);
            }
        }

        // ---- add positional term from staged U/W (double buffer) ----
#pragma unroll
        for (int nb = 0; nb < 4; nb++)
#pragma unroll
            for (int half = 0; half < 2; half++) {
                int col = hv * 64 + nb * 16 + half * 8 + (lane & 3) * 2;
                float2 u0 = *(const float2*)(uwc + i0 * 528 + col * 4);
                float2 u1 = *(const float2*)(uwc + i1 * 528 + col * 4);
                float2 w0 = *(const float2*)(uwc + 16896 + jl0 * 528 + col * 4);
                float2 w1 = *(const float2*)(uwc + 16896 + jl1 * 528 + col * 4);
                int f = nb * 2 + half;
                s[f][0] += u0.x + w0.x;
                s[f][1] += u0.y + w0.y;
                s[f][2] += u1.x + w1.x;
                s[f][3] += u1.y + w1.y;
            }

        // ---- per-warp online softmax (its key half only) ----
        float tmax0 = -1e30f, tmax1 = -1e30f;
#pragma unroll
        for (int f = 0; f < 8; f++) {
            tmax0 = fmaxf(tmax0, fmaxf(s[f][0], s[f][1]));
            tmax1 = fmaxf(tmax1, fmaxf(s[f][2], s[f][3]));
        }
        tmax0 = fmaxf(tmax0, __shfl_xor_sync(0xffffffffu, tmax0, 1));
        tmax0 = fmaxf(tmax0, __shfl_xor_sync(0xffffffffu, tmax0, 2));
        tmax1 = fmaxf(tmax1, __shfl_xor_sync(0xffffffffu, tmax1, 1));
        tmax1 = fmaxf(tmax1, __shfl_xor_sync(0xffffffffu, tmax1, 2));
        float mn0 = fmaxf(m0, tmax0), mn1 = fmaxf(m1, tmax1);
        float sc0 = __expf(m0 - mn0), sc1 = __expf(m1 - mn1);
        m0 = mn0; m1 = mn1;

        // p = 2^((s - mn) * log2e) via fp16x2 MUFU (2 weights per op)
        float b0s = mn0 * L2E, b1s = mn1 * L2E;
        uint32_t pf[8][2];
#pragma unroll
        for (int f = 0; f < 8; f++) {
            float e0 = fmaf(s[f][0], L2E, -b0s);
            float e1 = fmaf(s[f][1], L2E, -b0s);
            float e2 = fmaf(s[f][2], L2E, -b1s);
            float e3 = fmaf(s[f][3], L2E, -b1s);
            pf[f][0] = ex2h2(cvt2h(e1, e0));
            pf[f][1] = ex2h2(cvt2h(e3, e2));
        }
        lacc[0] *= sc0; lacc[1] *= sc0;
        lacc[2] *= sc1; lacc[3] *= sc1;
#pragma unroll
        for (int nf = 0; nf < 8; nf++) {
            y[nf][0] *= sc0; y[nf][1] *= sc0;
            y[nf][2] *= sc1; y[nf][3] *= sc1;
        }

        // ---- y += P @ V^T; l += P @ ones  (this warp's 64 keys) ----
#pragma unroll
        for (int ks = 0; ks < 4; ks++) {
            uint32_t a[4] = {pf[2 * ks][0], pf[2 * ks][1], pf[2 * ks + 1][0], pf[2 * ks + 1][1]};
            int vcol = hv * 8 + 2 * ks + (lane >> 4);
            mma_f16(lacc, a, onesb);
#pragma unroll
            for (int nb = 0; nb < 4; nb++) {
                uint32_t bf[4];
                ldsm4(bf, swzv(bb + 16384, nb * 16 + (lane & 15), vcol));
                uint32_t blo[2] = {bf[0], bf[2]}, bhi[2] = {bf[1], bf[3]};
                mma_f16(y[nb * 2], a, blo);
                mma_f16(y[nb * 2 + 1], a, bhi);
            }
        }
    }

    float l0 = lacc[0], l1 = lacc[2];

    // ---- epilogue: pairwise flash merge via smem, then store ----
    __syncthreads();   // KV/UW regions now free
    float* yst = (float*)(smem + FA_KV);            // [64 d][68 q] = 17408 B
    float* yb = (float*)(smem + FA_KV + 17408);     // [64 q][68 d] = 17408 B
    float* mb = (float*)(smem + FA_KV + 34816);     // 64 f32
    float* lb = mb + 64;
    int rl = rbase;

    if (hv == 1) {
#pragma unroll
        for (int nf = 0; nf < 8; nf++) {
            int d0 = nf * 8 + (lane & 3) * 2;
            yb[rl * 68 + d0] = y[nf][0];
            yb[rl * 68 + d0 + 1] = y[nf][1];
            yb[(rl + 8) * 68 + d0] = y[nf][2];
            yb[(rl + 8) * 68 + d0 + 1] = y[nf][3];
        }
        if ((lane & 3) == 0) {
            mb[rl] = m0; lb[rl] = l0;
            mb[rl + 8] = m1; lb[rl + 8] = l1;
        }
    }
    __syncthreads();

    if (hv == 0) {
        float mB0 = mb[rl], lB0 = lb[rl], mB1 = mb[rl + 8], lB1 = lb[rl + 8];
        float mf0 = fmaxf(m0, mB0), mf1 = fmaxf(m1, mB1);
        float fa0 = __expf(m0 - mf0), fb0 = __expf(mB0 - mf0);
        float fa1 = __expf(m1 - mf1), fb1 = __expf(mB1 - mf1);
        float inv0 = 1.f / (l0 * fa0 + lB0 * fb0);
        float inv1 = 1.f / (l1 * fa1 + lB1 * fb1);
        float sa0 = fa0 * inv0, sb0 = fb0 * inv0;
        float sa1 = fa1 * inv1, sb1 = fb1 * inv1;
#pragma unroll
        for (int nf = 0; nf < 8; nf++) {
            int d0 = nf * 8 + (lane & 3) * 2;
            yst[d0 * 68 + rl]       = y[nf][0] * sa0 + yb[rl * 68 + d0] * sb0;
            yst[(d0 + 1) * 68 + rl] = y[nf][1] * sa0 + yb[rl * 68 + d0 + 1] * sb0;
            yst[d0 * 68 + rl + 8]       = y[nf][2] * sa1 + yb[(rl + 8) * 68 + d0] * sb1;
            yst[(d0 + 1) * 68 + rl + 8] = y[nf][3] * sa1 + yb[(rl + 8) * 68 + d0 + 1] * sb1;
        }
    }
    __syncthreads();
    float* O = out + (size_t)(b * C_ + h * DH) * N_ + q0;
    for (int i = t; i < 1024; i += 256) {
        int d = i >> 4, qg = i & 15;
        float4 vv = *(float4*)&yst[d * 68 + qg * 4];
        *(float4*)&O[(size_t)d * N_ + qg * 4] = vv;
    }
}

// ---------------- launch ----------------
extern "C" void kernel_launch(void* const* d_in, const int* in_sizes, int n_in,
                              void* d_out, int out_size) {
    const float* x  = (const float*)d_in[0];
    const float* wq = (const float*)d_in[1];
    const float* bq = (const float*)d_in[2];
    const float* wk = (const float*)d_in[3];
    const float* bk = (const float*)d_in[4];
    const float* wv = (const float*)d_in[5];
    const float* bv = (const float*)d_in[6];
    const float* rh = (const float*)d_in[7];
    const float* rw = (const float*)d_in[8];

    cudaFuncSetAttribute(qkv_mma, cudaFuncAttributeMaxDynamicSharedMemorySize, SMEM_QKV);
    cudaFuncSetAttribute(uw_mma, cudaFuncAttributeMaxDynamicSharedMemorySize, SMEM_UW);
    cudaFuncSetAttribute(attn_fused, cudaFuncAttributeMaxDynamicSharedMemorySize, SMEM_FU);

    prep_all<<<7232, 256>>>(wq, wk, wv, rh, rw, x);
    qkv_mma<<<dim3(8, 2, 24), 512, SMEM_QKV>>>(bq, bk, bv);
    uw_mma<<<dim3(8, BH_), 256, SMEM_UW>>>();
    attn_fused<<<dim3(16, BH_), 256, SMEM_FU>>>((float*)d_out);
}